// round 10
// baseline (speedup 1.0000x reference)
#include <cuda_runtime.h>
#include <cstdint>

// ---------------------------------------------------------------------------
// Problem constants
// ---------------------------------------------------------------------------
#define BSZ    4
#define CCH    256
#define HH     48
#define WW     48
#define NPIX   2304          // 48*48
#define HEADS  8
#define DH     32
#define INNER  256
#define HID    128
#define LOG2E  1.4426950408889634f
#define QSC    (0.17677669529663687f * 1.4426950408889634f)

// ---------------------------------------------------------------------------
// Scratch
// ---------------------------------------------------------------------------
__device__ float g_Wt[4 * 256 * 256];          // tf32 patterns: wq,wk,wv,wproj
__device__ float g_xt[BSZ * CCH * NPIX];       // tf32 patterns of x
__device__ float g_W2t[9 * 128 * 128];         // tf32 w2 as [tap][oc][ic]
__device__ float g_luma[BSZ * NPIX];
__device__ float g_biasE[BSZ * NPIX];
__device__ float g_h1[BSZ * HID * NPIX];       // tf32-rounded conv1 output
__device__ float g_hmp2[24 * BSZ * HID];       // per-row-pair partial sums
__device__ float g_film[BSZ * 6 * 256];
__device__ float g_qkv[3 * BSZ * HEADS * NPIX * DH];   // [pr][b][h][n][d]; K,V tf32
__device__ float g_ao[BSZ * HEADS * NPIX * DH];        // tf32-rounded

#define PR_STRIDE (BSZ * HEADS * NPIX * DH)
#define BH_STRIDE (NPIX * DH)
#define B_STRIDE  (HEADS * NPIX * DH)

// ---------------------------------------------------------------------------
// Helpers
// ---------------------------------------------------------------------------
static __device__ __forceinline__ float ex2f(float x) {
    float r;
    asm("ex2.approx.f32 %0, %1;" : "=f"(r) : "f"(x));
    return r;
}
static __device__ __forceinline__ uint32_t tf32c(float f) {
    uint32_t u;
    asm("cvt.rna.tf32.f32 %0, %1;" : "=r"(u) : "f"(f));
    return u;
}
static __device__ __forceinline__ float tf32f(float f) {
    return __uint_as_float(tf32c(f));
}
static __device__ __forceinline__ void mma_tf32(float* d, const uint32_t* a,
                                                uint32_t b0, uint32_t b1) {
    asm("mma.sync.aligned.m16n8k8.row.col.f32.tf32.tf32.f32 "
        "{%0,%1,%2,%3}, {%4,%5,%6,%7}, {%8,%9}, {%0,%1,%2,%3};"
        : "+f"(d[0]), "+f"(d[1]), "+f"(d[2]), "+f"(d[3])
        : "r"(a[0]), "r"(a[1]), "r"(a[2]), "r"(a[3]), "r"(b0), "r"(b1));
}

// ---------------------------------------------------------------------------
// 0a) Prep: convert weights + x to tf32 bit patterns (layouts unchanged).
// ---------------------------------------------------------------------------
__global__ void k_prep(const float* __restrict__ wq, const float* __restrict__ wk,
                       const float* __restrict__ wv, const float* __restrict__ wp,
                       const float* __restrict__ x) {
    int i = blockIdx.x * 256 + threadIdx.x;
    float4 v, c;
    if (i < 65536) {
        int slot = i >> 14, j = i & 16383;
        const float* src = (slot == 0) ? wq : (slot == 1) ? wk : (slot == 2) ? wv : wp;
        v = ((const float4*)src)[j];
        c.x = tf32f(v.x); c.y = tf32f(v.y); c.z = tf32f(v.z); c.w = tf32f(v.w);
        ((float4*)g_Wt)[slot * 16384 + j] = c;
    } else {
        int j = i - 65536;
        v = ((const float4*)x)[j];
        c.x = tf32f(v.x); c.y = tf32f(v.y); c.z = tf32f(v.z); c.w = tf32f(v.w);
        ((float4*)g_xt)[j] = c;
    }
}

// ---------------------------------------------------------------------------
// 0b) Prep w2 -> [tap][oc][ic] tf32
// ---------------------------------------------------------------------------
__global__ void k_prepw2(const float* __restrict__ w2) {
    int i = blockIdx.x * 256 + threadIdx.x;   // < 147456
    int tap = i >> 14, r = i & 16383;
    int oc = r >> 7, ic = r & 127;
    g_W2t[i] = tf32f(w2[(oc * 128 + ic) * 9 + tap]);
}

// ---------------------------------------------------------------------------
// 1) Luma + key bias, fused
// ---------------------------------------------------------------------------
__global__ void k_lumabias(const float* __restrict__ rgb, const float* __restrict__ alpha_p) {
    __shared__ float sy[NPIX];
    __shared__ float pli[2500];
    __shared__ float red[256];
    int b = blockIdx.x, t = threadIdx.x;
    const float* rp = rgb + (size_t)b * 3 * NPIX;
    float lmn = 1e30f, lmx = -1e30f;
#pragma unroll
    for (int k = 0; k < 9; k++) {
        int p = t + k * 256;
        float y = 0.299f * rp[p] + 0.587f * rp[NPIX + p] + 0.114f * rp[2 * NPIX + p];
        sy[p] = y;
        lmn = fminf(lmn, y); lmx = fmaxf(lmx, y);
    }
    red[t] = lmn; __syncthreads();
    for (int s = 128; s > 0; s >>= 1) { if (t < s) red[t] = fminf(red[t], red[t + s]); __syncthreads(); }
    float mn = red[0]; __syncthreads();
    red[t] = lmx; __syncthreads();
    for (int s = 128; s > 0; s >>= 1) { if (t < s) red[t] = fmaxf(red[t], red[t + s]); __syncthreads(); }
    float mx = red[0]; __syncthreads();
    float inv = 1.0f / (mx - mn + 1e-6f);

    for (int i = t; i < 2500; i += 256) pli[i] = 0.f;
    __syncthreads();
#pragma unroll
    for (int k = 0; k < 9; k++) {
        int p = t + k * 256;
        float ln = (sy[p] - mn) * inv;
        g_luma[b * NPIX + p] = ln;
        pli[(p / 48 + 1) * 50 + (p % 48) + 1] = 1.0f - ln;
    }
    __syncthreads();
    float lsum = 0.f;
#pragma unroll
    for (int k = 0; k < 9; k++) {
        int p = t + k * 256;
        int bi = (p / 48 + 1) * 50 + (p % 48) + 1;
        float s = pli[bi - 51] + pli[bi - 50] + pli[bi - 49]
                + pli[bi - 1]  + pli[bi]      + pli[bi + 1]
                + pli[bi + 49] + pli[bi + 50] + pli[bi + 51];
        s *= (1.0f / 9.0f);
        sy[p] = s; lsum += s;
    }
    red[t] = lsum; __syncthreads();
    for (int s = 128; s > 0; s >>= 1) { if (t < s) red[t] += red[t + s]; __syncthreads(); }
    float mean = red[0] * (1.0f / (float)NPIX);
    float a = *alpha_p;
#pragma unroll
    for (int k = 0; k < 9; k++) {
        int p = t + k * 256;
        g_biasE[b * NPIX + p] = a * (sy[p] - mean) * LOG2E;
    }
}

// ---------------------------------------------------------------------------
// 2) Conv1: luma[1ch] -> h1[128ch] (tf32-rounded), 3x3 SAME, ReLU
// ---------------------------------------------------------------------------
__global__ void k_conv1(const float* __restrict__ w1, const float* __restrict__ b1) {
    __shared__ float pl[2500];
    int oc = blockIdx.x, b = blockIdx.y, t = threadIdx.x;
    for (int i = t; i < 2500; i += 256) pl[i] = 0.f;
    __syncthreads();
    const float* L = g_luma + b * NPIX;
#pragma unroll
    for (int k = 0; k < 9; k++) {
        int p = t + k * 256;
        pl[(p / 48 + 1) * 50 + (p % 48) + 1] = L[p];
    }
    __syncthreads();
    float w[9];
#pragma unroll
    for (int i = 0; i < 9; i++) w[i] = w1[oc * 9 + i];
    float bb = b1[oc];
    float* dst = g_h1 + ((size_t)(b * HID + oc)) * NPIX;
#pragma unroll
    for (int k = 0; k < 9; k++) {
        int p = t + k * 256;
        int bi = (p / 48 + 1) * 50 + (p % 48) + 1;
        float s = bb
            + pl[bi - 51] * w[0] + pl[bi - 50] * w[1] + pl[bi - 49] * w[2]
            + pl[bi - 1]  * w[3] + pl[bi]      * w[4] + pl[bi + 1]  * w[5]
            + pl[bi + 49] * w[6] + pl[bi + 50] * w[7] + pl[bi + 51] * w[8];
        dst[p] = tf32f(fmaxf(s, 0.f));
    }
}

// ---------------------------------------------------------------------------
// 3) Conv2 + ReLU + spatial-mean partials via tf32 mma (implicit im2col).
//    grid (24 row-pairs, 4 b), 256 thr = 8 warps. M=128 oc, N=96 px (2 rows),
//    K=1152 (9 taps x 128 ic). Shifted tap reads come free from the padded
//    smem tile. Partials -> g_hmp2[rp][b][oc].
// ---------------------------------------------------------------------------
#define HS_ICSTR 200     // 4*50; mod 32 == 8 -> conflict-free B frags
#define AW2_STR  36

__global__ __launch_bounds__(256) void k_conv2mma(const float* __restrict__ b2) {
    __shared__ float hsm[32 * HS_ICSTR];        // 32 ic x 4 rows x 50 (padded)
    __shared__ float asm2[128 * AW2_STR];       // 128 oc x 32 ic (padded)
    int rp = blockIdx.x, b = blockIdx.y;
    int t = threadIdx.x, warp = t >> 5, lane = t & 31;
    int gid = lane >> 2, tig = lane & 3;

    const float* h1b = g_h1 + (size_t)b * HID * NPIX;

    float s[12][4];
#pragma unroll
    for (int i = 0; i < 12; i++)
#pragma unroll
        for (int j = 0; j < 4; j++) s[i][j] = 0.f;

    // zero col padding (32 ic x 4 rows x 2 sides = 256 entries, one per thread)
    {
        int ic = t >> 3, r = (t >> 1) & 3, side = t & 1;
        hsm[ic * HS_ICSTR + r * 50 + side * 49] = 0.f;
    }

    for (int icc = 0; icc < 4; ++icc) {
        __syncthreads();
        // stage h1 tile: 32 ic x rows (rp*2-1 .. rp*2+2) x 48
        {
            int pair = t >> 1, half = t & 1;
            int ic = pair >> 2, r = pair & 3;
            int gr = rp * 2 - 1 + r;
            float* dst = &hsm[ic * HS_ICSTR + r * 50 + 1 + half * 24];
            if (gr >= 0 && gr < 48) {
                const float* src = &h1b[(size_t)(icc * 32 + ic) * NPIX + gr * 48 + half * 24];
#pragma unroll
                for (int j = 0; j < 6; j++) {
                    float4 v = *(const float4*)&src[j * 4];
                    dst[j * 4 + 0] = v.x; dst[j * 4 + 1] = v.y;
                    dst[j * 4 + 2] = v.z; dst[j * 4 + 3] = v.w;
                }
            } else {
#pragma unroll
                for (int j = 0; j < 24; j++) dst[j] = 0.f;
            }
        }
        for (int tap = 0; tap < 9; ++tap) {
            __syncthreads();
            // stage A = W2t[tap][0..127][icc*32..+32]
            {
                const float* W = g_W2t + tap * 16384 + icc * 32;
#pragma unroll
                for (int j = 0; j < 4; j++) {
                    int idx = t + j * 256;
                    int o = idx >> 3, cg = idx & 7;
                    *(float4*)&asm2[o * AW2_STR + cg * 4] = *(const float4*)&W[o * 128 + cg * 4];
                }
            }
            __syncthreads();
            int dr = tap / 3 - 1, dc = tap % 3 - 1;
#pragma unroll
            for (int ks = 0; ks < 4; ks++) {
                uint32_t a[4];
                int ab = (warp * 16 + gid) * AW2_STR + ks * 8 + tig;
                a[0] = __float_as_uint(asm2[ab]);
                a[1] = __float_as_uint(asm2[ab + 8 * AW2_STR]);
                a[2] = __float_as_uint(asm2[ab + 4]);
                a[3] = __float_as_uint(asm2[ab + 8 * AW2_STR + 4]);
                int kb0 = (ks * 8 + tig) * HS_ICSTR;
#pragma unroll
                for (int nt = 0; nt < 12; nt++) {
                    int rowt = (nt < 6) ? 0 : 1;
                    int base = (rowt + dr + 1) * 50 + dc + 1 + (nt % 6) * 8 + gid;
                    uint32_t b0 = __float_as_uint(hsm[kb0 + base]);
                    uint32_t b1 = __float_as_uint(hsm[kb0 + 4 * HS_ICSTR + base]);
                    mma_tf32(s[nt], a, b0, b1);
                }
            }
        }
    }
    // bias + ReLU + partial spatial sum (quad-reduce over tig)
    int oc0 = warp * 16 + gid, oc1 = oc0 + 8;
    float bb0 = b2[oc0], bb1 = b2[oc1];
    float p0 = 0.f, p1 = 0.f;
#pragma unroll
    for (int nt = 0; nt < 12; nt++) {
        p0 += fmaxf(s[nt][0] + bb0, 0.f) + fmaxf(s[nt][1] + bb0, 0.f);
        p1 += fmaxf(s[nt][2] + bb1, 0.f) + fmaxf(s[nt][3] + bb1, 0.f);
    }
    p0 += __shfl_xor_sync(0xffffffffu, p0, 1);
    p0 += __shfl_xor_sync(0xffffffffu, p0, 2);
    p1 += __shfl_xor_sync(0xffffffffu, p1, 1);
    p1 += __shfl_xor_sync(0xffffffffu, p1, 2);
    if (tig == 0) {
        float* dst = g_hmp2 + ((size_t)rp * BSZ + b) * HID;
        dst[oc0] = p0;
        dst[oc1] = p1;
    }
}

// ---------------------------------------------------------------------------
// 4) FiLM parameter GEMVs (sums 24 conv2 row-pair partials)
// ---------------------------------------------------------------------------
struct FilmArgs { const float* w[6]; const float* b[6]; };

__global__ void k_film(FilmArgs fa) {
    int s = blockIdx.x, b = blockIdx.y, o = threadIdx.x;
    __shared__ float sh[HID];
    if (threadIdx.x < HID) {
        int h = threadIdx.x;
        float acc = 0.f;
#pragma unroll
        for (int rp = 0; rp < 24; rp++) acc += g_hmp2[((size_t)rp * BSZ + b) * HID + h];
        sh[h] = acc * (1.0f / (float)NPIX);
    }
    __syncthreads();
    const float* W = fa.w[s] + o * HID;
    float acc = fa.b[s][o];
#pragma unroll 8
    for (int h = 0; h < HID; h++) acc += sh[h] * W[h];
    g_film[(b * 6 + s) * 256 + o] = acc;
}

// ---------------------------------------------------------------------------
// 5) QKV GEMM via tf32 mma (+ bias + FiLM)
// ---------------------------------------------------------------------------
#define AW_STRIDE 36
#define BX_STRIDE 72

__global__ __launch_bounds__(256) void k_qkv(const float* __restrict__ bq,
                                             const float* __restrict__ bk,
                                             const float* __restrict__ bv) {
    __shared__ float wsm[128 * AW_STRIDE];
    __shared__ float xsm[32 * BX_STRIDE];
    int ntb = blockIdx.x, mt = blockIdx.y, z = blockIdx.z;
    int pr = z >> 2, b = z & 3;
    int t = threadIdx.x, warp = t >> 5, lane = t & 31;
    int gid = lane >> 2, tig = lane & 3;
    int n0 = ntb * 64;

    const float* W = g_Wt + pr * 65536 + mt * 128 * 256;
    const float* xb = g_xt + (size_t)b * CCH * NPIX;

    float s[8][4];
#pragma unroll
    for (int i = 0; i < 8; i++)
#pragma unroll
        for (int j = 0; j < 4; j++) s[i][j] = 0.f;

    for (int kk = 0; kk < 256; kk += 32) {
        if (kk) __syncthreads();
#pragma unroll
        for (int j = 0; j < 4; j++) {
            int idx = t + j * 256;
            int o = idx >> 3, cg = idx & 7;
            *(float4*)&wsm[o * AW_STRIDE + cg * 4] = *(const float4*)&W[o * 256 + kk + cg * 4];
        }
#pragma unroll
        for (int j = 0; j < 2; j++) {
            int idx = t + j * 256;
            int c = idx >> 4, ng = idx & 15;
            *(float4*)&xsm[c * BX_STRIDE + ng * 4] =
                *(const float4*)&xb[(size_t)(kk + c) * NPIX + n0 + ng * 4];
        }
        __syncthreads();
#pragma unroll
        for (int ks = 0; ks < 4; ks++) {
            uint32_t a[4];
            int ab = (warp * 16 + gid) * AW_STRIDE + ks * 8 + tig;
            a[0] = __float_as_uint(wsm[ab]);
            a[1] = __float_as_uint(wsm[ab + 8 * AW_STRIDE]);
            a[2] = __float_as_uint(wsm[ab + 4]);
            a[3] = __float_as_uint(wsm[ab + 8 * AW_STRIDE + 4]);
#pragma unroll
            for (int nt = 0; nt < 8; nt++) {
                int bbx = (ks * 8 + tig) * BX_STRIDE + nt * 8 + gid;
                mma_tf32(s[nt], a, __float_as_uint(xsm[bbx]),
                         __float_as_uint(xsm[bbx + 4 * BX_STRIDE]));
            }
        }
    }
    int o0 = mt * 128 + warp * 16 + gid, o1 = o0 + 8;
    const float* fg  = g_film + (b * 6 + 2 * pr) * 256;
    const float* fb2 = g_film + (b * 6 + 2 * pr + 1) * 256;
    const float* bias = (pr == 0) ? bq : (pr == 1) ? bk : bv;
    float g0 = fg[o0], g1 = fg[o1], e0 = fb2[o0], e1 = fb2[o1];
    float i0 = bias[o0], i1 = bias[o1];
    int h0 = o0 >> 5, d0 = o0 & 31, h1 = o1 >> 5, d1 = o1 & 31;
    float* outb = g_qkv + (size_t)pr * PR_STRIDE + (size_t)b * B_STRIDE;
    bool rnd = (pr != 0);
#pragma unroll
    for (int nt = 0; nt < 8; nt++) {
        int n = n0 + nt * 8 + 2 * tig;
        float v00 = g0 * (s[nt][0] + i0) + e0;
        float v01 = g0 * (s[nt][1] + i0) + e0;
        float v10 = g1 * (s[nt][2] + i1) + e1;
        float v11 = g1 * (s[nt][3] + i1) + e1;
        if (rnd) { v00 = tf32f(v00); v01 = tf32f(v01); v10 = tf32f(v10); v11 = tf32f(v11); }
        outb[((size_t)h0 * NPIX + n) * 32 + d0]     = v00;
        outb[((size_t)h0 * NPIX + n + 1) * 32 + d0] = v01;
        outb[((size_t)h1 * NPIX + n) * 32 + d1]     = v10;
        outb[((size_t)h1 * NPIX + n + 1) * 32 + d1] = v11;
    }
}

// ---------------------------------------------------------------------------
// 6) Flash attention with tf32 mma
// ---------------------------------------------------------------------------
#define KS_STRIDE 36
#define VS_STRIDE 40
#define PS_STRIDE 68
#define ATTN_SMEM ((64 * KS_STRIDE + 64 * VS_STRIDE + 8 * 16 * PS_STRIDE + 64) * 4)

__global__ __launch_bounds__(256) void k_attn() {
    extern __shared__ float smp[];
    float* ksm = smp;
    float* vsm = ksm + 64 * KS_STRIDE;
    float* psm = vsm + 64 * VS_STRIDE;
    float* bsm = psm + 8 * 16 * PS_STRIDE;

    int t = threadIdx.x;
    int warp = t >> 5, lane = t & 31;
    int gid = lane >> 2, tig = lane & 3;
    int bh = blockIdx.y;
    int b = bh >> 3;

    const float* Qb = g_qkv + (size_t)bh * BH_STRIDE;
    const float* Kb = g_qkv + (size_t)PR_STRIDE + (size_t)bh * BH_STRIDE;
    const float* Vb = g_qkv + (size_t)2 * PR_STRIDE + (size_t)bh * BH_STRIDE;
    const float* bE = g_biasE + b * NPIX;

    int qr = blockIdx.x * 128 + warp * 16 + gid;

    uint32_t aq[4][4];
#pragma unroll
    for (int ks = 0; ks < 4; ks++) {
        aq[ks][0] = tf32c(Qb[(size_t)qr * 32 + ks * 8 + tig] * QSC);
        aq[ks][1] = tf32c(Qb[(size_t)(qr + 8) * 32 + ks * 8 + tig] * QSC);
        aq[ks][2] = tf32c(Qb[(size_t)qr * 32 + ks * 8 + tig + 4] * QSC);
        aq[ks][3] = tf32c(Qb[(size_t)(qr + 8) * 32 + ks * 8 + tig + 4] * QSC);
    }

    float o[4][4];
#pragma unroll
    for (int i = 0; i < 4; i++)
#pragma unroll
        for (int j = 0; j < 4; j++) o[i][j] = 0.f;
    float m0 = -1e30f, m1 = -1e30f, l0 = 0.f, l1 = 0.f;

    float* pw = psm + warp * 16 * PS_STRIDE;

    for (int nk = 0; nk < 36; ++nk) {
        const float4* Kg = (const float4*)Kb + nk * 512;
        const float4* Vg = (const float4*)Vb + nk * 512;
#pragma unroll
        for (int i = t; i < 512; i += 256) {
            int key = i >> 3, dq = i & 7;
            *(float4*)&ksm[key * KS_STRIDE + dq * 4] = Kg[i];
            *(float4*)&vsm[key * VS_STRIDE + dq * 4] = Vg[i];
        }
        if (t < 64) bsm[t] = bE[nk * 64 + t];
        __syncthreads();

        float s[8][4];
#pragma unroll
        for (int nt = 0; nt < 8; nt++)
#pragma unroll
            for (int c = 0; c < 4; c++) s[nt][c] = 0.f;
#pragma unroll
        for (int ks = 0; ks < 4; ks++) {
#pragma unroll
            for (int nt = 0; nt < 8; nt++) {
                int kb = (nt * 8 + gid) * KS_STRIDE + ks * 8 + tig;
                uint32_t b0 = __float_as_uint(ksm[kb]);
                uint32_t b1 = __float_as_uint(ksm[kb + 4]);
                mma_tf32(s[nt], aq[ks], b0, b1);
            }
        }
        float mx0 = -1e30f, mx1 = -1e30f;
#pragma unroll
        for (int nt = 0; nt < 8; nt++) {
            float b0v = bsm[nt * 8 + 2 * tig];
            float b1v = bsm[nt * 8 + 2 * tig + 1];
            s[nt][0] += b0v; s[nt][1] += b1v;
            s[nt][2] += b0v; s[nt][3] += b1v;
            mx0 = fmaxf(mx0, fmaxf(s[nt][0], s[nt][1]));
            mx1 = fmaxf(mx1, fmaxf(s[nt][2], s[nt][3]));
        }
        mx0 = fmaxf(mx0, __shfl_xor_sync(0xffffffffu, mx0, 1));
        mx0 = fmaxf(mx0, __shfl_xor_sync(0xffffffffu, mx0, 2));
        mx1 = fmaxf(mx1, __shfl_xor_sync(0xffffffffu, mx1, 1));
        mx1 = fmaxf(mx1, __shfl_xor_sync(0xffffffffu, mx1, 2));

        float mn0 = fmaxf(m0, mx0), mn1 = fmaxf(m1, mx1);
        float c0 = ex2f(m0 - mn0), c1 = ex2f(m1 - mn1);
        m0 = mn0; m1 = mn1;

        float rs0 = 0.f, rs1 = 0.f;
#pragma unroll
        for (int nt = 0; nt < 8; nt++) {
            float p00 = ex2f(s[nt][0] - mn0);
            float p01 = ex2f(s[nt][1] - mn0);
            float p10 = ex2f(s[nt][2] - mn1);
            float p11 = ex2f(s[nt][3] - mn1);
            rs0 += p00 + p01; rs1 += p10 + p11;
            float2 lo, hi;
            lo.x = tf32f(p00); lo.y = tf32f(p01);
            hi.x = tf32f(p10); hi.y = tf32f(p11);
            *(float2*)&pw[gid * PS_STRIDE + nt * 8 + 2 * tig] = lo;
            *(float2*)&pw[(gid + 8) * PS_STRIDE + nt * 8 + 2 * tig] = hi;
        }
        rs0 += __shfl_xor_sync(0xffffffffu, rs0, 1);
        rs0 += __shfl_xor_sync(0xffffffffu, rs0, 2);
        rs1 += __shfl_xor_sync(0xffffffffu, rs1, 1);
        rs1 += __shfl_xor_sync(0xffffffffu, rs1, 2);
        l0 = l0 * c0 + rs0;
        l1 = l1 * c1 + rs1;
#pragma unroll
        for (int nt = 0; nt < 4; nt++) {
            o[nt][0] *= c0; o[nt][1] *= c0;
            o[nt][2] *= c1; o[nt][3] *= c1;
        }
        __syncwarp();

#pragma unroll
        for (int ks = 0; ks < 8; ks++) {
            uint32_t a[4];
            a[0] = __float_as_uint(pw[gid * PS_STRIDE + ks * 8 + tig]);
            a[1] = __float_as_uint(pw[(gid + 8) * PS_STRIDE + ks * 8 + tig]);
            a[2] = __float_as_uint(pw[gid * PS_STRIDE + ks * 8 + tig + 4]);
            a[3] = __float_as_uint(pw[(gid + 8) * PS_STRIDE + ks * 8 + tig + 4]);
#pragma unroll
            for (int nt = 0; nt < 4; nt++) {
                int vb = (ks * 8 + tig) * VS_STRIDE + nt * 8 + gid;
                uint32_t b0 = __float_as_uint(vsm[vb]);
                uint32_t b1 = __float_as_uint(vsm[vb + 4 * VS_STRIDE]);
                mma_tf32(o[nt], a, b0, b1);
            }
        }
        __syncthreads();
    }

    float i0 = 1.0f / l0, i1 = 1.0f / l1;
    float* AO = g_ao + (size_t)bh * BH_STRIDE;
#pragma unroll
    for (int nt = 0; nt < 4; nt++) {
        float2 lo = make_float2(tf32f(o[nt][0] * i0), tf32f(o[nt][1] * i0));
        float2 hi = make_float2(tf32f(o[nt][2] * i1), tf32f(o[nt][3] * i1));
        *(float2*)&AO[(size_t)qr * 32 + nt * 8 + 2 * tig] = lo;
        *(float2*)&AO[(size_t)(qr + 8) * 32 + nt * 8 + 2 * tig] = hi;
    }
}

// ---------------------------------------------------------------------------
// 7) Output projection via tf32 mma
// ---------------------------------------------------------------------------
__global__ __launch_bounds__(256) void k_proj(const float* __restrict__ bproj,
                                              float* __restrict__ out) {
    __shared__ float wsm[128 * AW_STRIDE];
    __shared__ float bsm2[32 * BX_STRIDE];
    int ntb = blockIdx.x, mt = blockIdx.y, b = blockIdx.z;
    int t = threadIdx.x, warp = t >> 5, lane = t & 31;
    int gid = lane >> 2, tig = lane & 3;
    int n0 = ntb * 64;

    const float* W = g_Wt + 3 * 65536 + mt * 128 * 256;
    const float* AOb = g_ao + (size_t)b * B_STRIDE;

    float s[8][4];
#pragma unroll
    for (int i = 0; i < 8; i++)
#pragma unroll
        for (int j = 0; j < 4; j++) s[i][j] = 0.f;

    for (int kk = 0; kk < 256; kk += 32) {
        if (kk) __syncthreads();
#pragma unroll
        for (int j = 0; j < 4; j++) {
            int idx = t + j * 256;
            int o = idx >> 3, cg = idx & 7;
            *(float4*)&wsm[o * AW_STRIDE + cg * 4] = *(const float4*)&W[o * 256 + kk + cg * 4];
        }
#pragma unroll
        for (int j = 0; j < 8; j++) {
            int idx = t + j * 256;
            int c = idx >> 6, ng = idx & 63;
            int o = kk + c;
            bsm2[c * BX_STRIDE + ng] =
                AOb[((size_t)(o >> 5) * NPIX + n0 + ng) * 32 + (o & 31)];
        }
        __syncthreads();
#pragma unroll
        for (int ks = 0; ks < 4; ks++) {
            uint32_t a[4];
            int ab = (warp * 16 + gid) * AW_STRIDE + ks * 8 + tig;
            a[0] = __float_as_uint(wsm[ab]);
            a[1] = __float_as_uint(wsm[ab + 8 * AW_STRIDE]);
            a[2] = __float_as_uint(wsm[ab + 4]);
            a[3] = __float_as_uint(wsm[ab + 8 * AW_STRIDE + 4]);
#pragma unroll
            for (int nt = 0; nt < 8; nt++) {
                int bbx = (ks * 8 + tig) * BX_STRIDE + nt * 8 + gid;
                mma_tf32(s[nt], a, __float_as_uint(bsm2[bbx]),
                         __float_as_uint(bsm2[bbx + 4 * BX_STRIDE]));
            }
        }
    }
    int o0 = mt * 128 + warp * 16 + gid, o1 = o0 + 8;
    float bp0 = bproj[o0], bp1 = bproj[o1];
#pragma unroll
    for (int nt = 0; nt < 8; nt++) {
        int n = n0 + nt * 8 + 2 * tig;
        *(float2*)&out[((size_t)(b * 256 + o0)) * NPIX + n] =
            make_float2(s[nt][0] + bp0, s[nt][1] + bp0);
        *(float2*)&out[((size_t)(b * 256 + o1)) * NPIX + n] =
            make_float2(s[nt][2] + bp1, s[nt][3] + bp1);
    }
}

// ---------------------------------------------------------------------------
// launch
// ---------------------------------------------------------------------------
extern "C" void kernel_launch(void* const* d_in, const int* in_sizes, int n_in,
                              void* d_out, int out_size) {
    const float* x     = (const float*)d_in[0];
    const float* rgb   = (const float*)d_in[1];
    const float* wq    = (const float*)d_in[2];
    const float* bq    = (const float*)d_in[3];
    const float* wk    = (const float*)d_in[4];
    const float* bk    = (const float*)d_in[5];
    const float* wv    = (const float*)d_in[6];
    const float* bv    = (const float*)d_in[7];
    const float* wproj = (const float*)d_in[8];
    const float* bproj = (const float*)d_in[9];
    const float* c1w   = (const float*)d_in[10];
    const float* c1b   = (const float*)d_in[11];
    const float* c2w   = (const float*)d_in[12];
    const float* c2b   = (const float*)d_in[13];
    const float* alpha = (const float*)d_in[26];

    FilmArgs fa;
    fa.w[0] = (const float*)d_in[14]; fa.b[0] = (const float*)d_in[15];
    fa.w[1] = (const float*)d_in[16]; fa.b[1] = (const float*)d_in[17];
    fa.w[2] = (const float*)d_in[18]; fa.b[2] = (const float*)d_in[19];
    fa.w[3] = (const float*)d_in[20]; fa.b[3] = (const float*)d_in[21];
    fa.w[4] = (const float*)d_in[22]; fa.b[4] = (const float*)d_in[23];
    fa.w[5] = (const float*)d_in[24]; fa.b[5] = (const float*)d_in[25];

    static bool attr_done = false;
    if (!attr_done) {
        cudaFuncSetAttribute(k_attn, cudaFuncAttributeMaxDynamicSharedMemorySize, ATTN_SMEM);
        attr_done = true;
    }

    k_prep<<<2560, 256>>>(wq, wk, wv, wproj, x);
    k_prepw2<<<576, 256>>>(c2w);
    k_lumabias<<<BSZ, 256>>>(rgb, alpha);
    k_conv1<<<dim3(HID, BSZ), 256>>>(c1w, c1b);
    k_conv2mma<<<dim3(24, BSZ), 256>>>(c2b);
    k_film<<<dim3(6, BSZ), 256>>>(fa);
    k_qkv<<<dim3(36, 2, 12), 256>>>(bq, bk, bv);
    k_attn<<<dim3(18, 32), 256, ATTN_SMEM>>>();
    k_proj<<<dim3(36, 2, 4), 256>>>(bproj, (float*)d_out);
}

// round 11
// speedup vs baseline: 1.3558x; 1.3558x over previous
#include <cuda_runtime.h>
#include <cstdint>

// ---------------------------------------------------------------------------
// Problem constants
// ---------------------------------------------------------------------------
#define BSZ    4
#define CCH    256
#define HH     48
#define WW     48
#define NPIX   2304          // 48*48
#define HEADS  8
#define DH     32
#define INNER  256
#define HID    128
#define LOG2E  1.4426950408889634f
#define QSC    (0.17677669529663687f * 1.4426950408889634f)

// ---------------------------------------------------------------------------
// Scratch
// ---------------------------------------------------------------------------
__device__ float g_Wt[4 * 256 * 256];          // tf32 patterns: wq,wk,wv,wproj
__device__ float g_xt[BSZ * CCH * NPIX];       // tf32 patterns of x
__device__ float g_luma[BSZ * NPIX];
__device__ float g_biasE[BSZ * NPIX];
__device__ float g_h1[BSZ * HID * NPIX];
__device__ float g_hmp[6 * BSZ * HID];         // 6 band partials
__device__ float g_film[BSZ * 6 * 256];
__device__ float g_qkv[3 * BSZ * HEADS * NPIX * DH];   // [pr][b][h][n][d]; K,V tf32
__device__ float g_ao[BSZ * HEADS * NPIX * DH];        // tf32-rounded

#define PR_STRIDE (BSZ * HEADS * NPIX * DH)
#define BH_STRIDE (NPIX * DH)
#define B_STRIDE  (HEADS * NPIX * DH)

// ---------------------------------------------------------------------------
// Helpers
// ---------------------------------------------------------------------------
static __device__ __forceinline__ float2 ffma2(float2 a, float2 b, float2 c) {
    float2 d;
    asm("fma.rn.f32x2 %0, %1, %2, %3;"
        : "=l"(reinterpret_cast<unsigned long long&>(d))
        : "l"(reinterpret_cast<unsigned long long&>(a)),
          "l"(reinterpret_cast<unsigned long long&>(b)),
          "l"(reinterpret_cast<unsigned long long&>(c)));
    return d;
}
static __device__ __forceinline__ float ex2f(float x) {
    float r;
    asm("ex2.approx.f32 %0, %1;" : "=f"(r) : "f"(x));
    return r;
}
static __device__ __forceinline__ uint32_t tf32c(float f) {
    uint32_t u;
    asm("cvt.rna.tf32.f32 %0, %1;" : "=r"(u) : "f"(f));
    return u;
}
static __device__ __forceinline__ float tf32f(float f) {
    return __uint_as_float(tf32c(f));
}
static __device__ __forceinline__ void mma_tf32(float* d, const uint32_t* a,
                                                uint32_t b0, uint32_t b1) {
    asm("mma.sync.aligned.m16n8k8.row.col.f32.tf32.tf32.f32 "
        "{%0,%1,%2,%3}, {%4,%5,%6,%7}, {%8,%9}, {%0,%1,%2,%3};"
        : "+f"(d[0]), "+f"(d[1]), "+f"(d[2]), "+f"(d[3])
        : "r"(a[0]), "r"(a[1]), "r"(a[2]), "r"(a[3]), "r"(b0), "r"(b1));
}

// ---------------------------------------------------------------------------
// 0) Prep: convert weights + x to tf32 bit patterns (layouts unchanged).
// ---------------------------------------------------------------------------
__global__ void k_prep(const float* __restrict__ wq, const float* __restrict__ wk,
                       const float* __restrict__ wv, const float* __restrict__ wp,
                       const float* __restrict__ x) {
    int i = blockIdx.x * 256 + threadIdx.x;
    float4 v, c;
    if (i < 65536) {
        int slot = i >> 14, j = i & 16383;
        const float* src = (slot == 0) ? wq : (slot == 1) ? wk : (slot == 2) ? wv : wp;
        v = ((const float4*)src)[j];
        c.x = tf32f(v.x); c.y = tf32f(v.y); c.z = tf32f(v.z); c.w = tf32f(v.w);
        ((float4*)g_Wt)[slot * 16384 + j] = c;
    } else {
        int j = i - 65536;
        v = ((const float4*)x)[j];
        c.x = tf32f(v.x); c.y = tf32f(v.y); c.z = tf32f(v.z); c.w = tf32f(v.w);
        ((float4*)g_xt)[j] = c;
    }
}

// ---------------------------------------------------------------------------
// 1) Luma + key bias, fused
// ---------------------------------------------------------------------------
__global__ void k_lumabias(const float* __restrict__ rgb, const float* __restrict__ alpha_p) {
    __shared__ float sy[NPIX];
    __shared__ float pli[2500];
    __shared__ float red[256];
    int b = blockIdx.x, t = threadIdx.x;
    const float* rp = rgb + (size_t)b * 3 * NPIX;
    float lmn = 1e30f, lmx = -1e30f;
#pragma unroll
    for (int k = 0; k < 9; k++) {
        int p = t + k * 256;
        float y = 0.299f * rp[p] + 0.587f * rp[NPIX + p] + 0.114f * rp[2 * NPIX + p];
        sy[p] = y;
        lmn = fminf(lmn, y); lmx = fmaxf(lmx, y);
    }
    red[t] = lmn; __syncthreads();
    for (int s = 128; s > 0; s >>= 1) { if (t < s) red[t] = fminf(red[t], red[t + s]); __syncthreads(); }
    float mn = red[0]; __syncthreads();
    red[t] = lmx; __syncthreads();
    for (int s = 128; s > 0; s >>= 1) { if (t < s) red[t] = fmaxf(red[t], red[t + s]); __syncthreads(); }
    float mx = red[0]; __syncthreads();
    float inv = 1.0f / (mx - mn + 1e-6f);

    for (int i = t; i < 2500; i += 256) pli[i] = 0.f;
    __syncthreads();
#pragma unroll
    for (int k = 0; k < 9; k++) {
        int p = t + k * 256;
        float ln = (sy[p] - mn) * inv;
        g_luma[b * NPIX + p] = ln;
        pli[(p / 48 + 1) * 50 + (p % 48) + 1] = 1.0f - ln;
    }
    __syncthreads();
    float lsum = 0.f;
#pragma unroll
    for (int k = 0; k < 9; k++) {
        int p = t + k * 256;
        int bi = (p / 48 + 1) * 50 + (p % 48) + 1;
        float s = pli[bi - 51] + pli[bi - 50] + pli[bi - 49]
                + pli[bi - 1]  + pli[bi]      + pli[bi + 1]
                + pli[bi + 49] + pli[bi + 50] + pli[bi + 51];
        s *= (1.0f / 9.0f);
        sy[p] = s; lsum += s;
    }
    red[t] = lsum; __syncthreads();
    for (int s = 128; s > 0; s >>= 1) { if (t < s) red[t] += red[t + s]; __syncthreads(); }
    float mean = red[0] * (1.0f / (float)NPIX);
    float a = *alpha_p;
#pragma unroll
    for (int k = 0; k < 9; k++) {
        int p = t + k * 256;
        g_biasE[b * NPIX + p] = a * (sy[p] - mean) * LOG2E;
    }
}

// ---------------------------------------------------------------------------
// 2) Conv1: luma[1ch] -> h1[128ch], 3x3 SAME, ReLU
// ---------------------------------------------------------------------------
__global__ void k_conv1(const float* __restrict__ w1, const float* __restrict__ b1) {
    __shared__ float pl[2500];
    int oc = blockIdx.x, b = blockIdx.y, t = threadIdx.x;
    for (int i = t; i < 2500; i += 256) pl[i] = 0.f;
    __syncthreads();
    const float* L = g_luma + b * NPIX;
#pragma unroll
    for (int k = 0; k < 9; k++) {
        int p = t + k * 256;
        pl[(p / 48 + 1) * 50 + (p % 48) + 1] = L[p];
    }
    __syncthreads();
    float w[9];
#pragma unroll
    for (int i = 0; i < 9; i++) w[i] = w1[oc * 9 + i];
    float bb = b1[oc];
    float* dst = g_h1 + ((size_t)(b * HID + oc)) * NPIX;
#pragma unroll
    for (int k = 0; k < 9; k++) {
        int p = t + k * 256;
        int bi = (p / 48 + 1) * 50 + (p % 48) + 1;
        float s = bb
            + pl[bi - 51] * w[0] + pl[bi - 50] * w[1] + pl[bi - 49] * w[2]
            + pl[bi - 1]  * w[3] + pl[bi]      * w[4] + pl[bi + 1]  * w[5]
            + pl[bi + 49] * w[6] + pl[bi + 50] * w[7] + pl[bi + 51] * w[8];
        dst[p] = fmaxf(s, 0.f);
    }
}

// ---------------------------------------------------------------------------
// 3) Conv2 + ReLU + spatial mean (band partials), software-pipelined ic loop.
//    grid (32 ocg, 4 b, 6 band), block (16,8) = 128 thr. 8 rows per band.
// ---------------------------------------------------------------------------
__global__ __launch_bounds__(128) void k_conv2mean(const float* __restrict__ w2,
                                                   const float* __restrict__ b2) {
    __shared__ float wsm[128 * 36];   // [ic][tap][oc4]
    int ocg = blockIdx.x, b = blockIdx.y, band = blockIdx.z;
    int tx = threadIdx.x, ty = threadIdx.y;
    int t = ty * 16 + tx;

    for (int i = t; i < 128 * 36; i += 128) {
        int ic = i / 36, r = i % 36;
        int tap = r >> 2, oc = r & 3;
        wsm[i] = w2[(((ocg * 4 + oc) * 128) + ic) * 9 + tap];
    }
    __syncthreads();

    int row = band * 8 + ty;
    int col0 = tx * 4;
    bool active = (tx < 12);
    const float* srcb = g_h1 + ((size_t)(b * HID)) * NPIX;

    float2 acc2[4][2];
#pragma unroll
    for (int j = 0; j < 4; j++) { acc2[j][0] = make_float2(0.f, 0.f); acc2[j][1] = make_float2(0.f, 0.f); }

    // preload ic = 0
    float4 h[3];
#pragma unroll
    for (int r = 0; r < 3; r++) {
        int rr = row - 1 + r;
        float4 hv = make_float4(0.f, 0.f, 0.f, 0.f);
        if (active && rr >= 0 && rr < 48) hv = *(const float4*)&srcb[rr * 48 + col0];
        h[r] = hv;
    }

    for (int ic = 0; ic < 128; ++ic) {
        float4 hn[3];
        if (ic < 127) {
            const float* sn = srcb + (size_t)(ic + 1) * NPIX;
#pragma unroll
            for (int r = 0; r < 3; r++) {
                int rr = row - 1 + r;
                float4 hv = make_float4(0.f, 0.f, 0.f, 0.f);
                if (active && rr >= 0 && rr < 48) hv = *(const float4*)&sn[rr * 48 + col0];
                hn[r] = hv;
            }
        }
        float hl[3], hr[3];
#pragma unroll
        for (int r = 0; r < 3; r++) {
            float l = __shfl_up_sync(0xffffffffu, h[r].w, 1);
            float rt = __shfl_down_sync(0xffffffffu, h[r].x, 1);
            hl[r] = (tx == 0) ? 0.f : l;
            hr[r] = (tx >= 11) ? 0.f : rt;
        }
        const float4* wv = (const float4*)&wsm[ic * 36];
#pragma unroll
        for (int r = 0; r < 3; r++) {
            float v[6] = { hl[r], h[r].x, h[r].y, h[r].z, h[r].w, hr[r] };
#pragma unroll
            for (int tc = 0; tc < 3; tc++) {
                float4 w4 = wv[r * 3 + tc];
                float2 wlo = make_float2(w4.x, w4.y), whi = make_float2(w4.z, w4.w);
#pragma unroll
                for (int j = 0; j < 4; j++) {
                    float vv = v[j + tc];
                    float2 tt = make_float2(vv, vv);
                    acc2[j][0] = ffma2(tt, wlo, acc2[j][0]);
                    acc2[j][1] = ffma2(tt, whi, acc2[j][1]);
                }
            }
        }
#pragma unroll
        for (int r = 0; r < 3; r++) h[r] = hn[r];
    }
    float bb[4] = { b2[ocg * 4 + 0], b2[ocg * 4 + 1], b2[ocg * 4 + 2], b2[ocg * 4 + 3] };
    float prt[4] = { 0.f, 0.f, 0.f, 0.f };
    if (active) {
#pragma unroll
        for (int j = 0; j < 4; j++) {
            prt[0] += fmaxf(acc2[j][0].x + bb[0], 0.f);
            prt[1] += fmaxf(acc2[j][0].y + bb[1], 0.f);
            prt[2] += fmaxf(acc2[j][1].x + bb[2], 0.f);
            prt[3] += fmaxf(acc2[j][1].y + bb[3], 0.f);
        }
    }
    __syncthreads();
    for (int oc = 0; oc < 4; oc++) {
        wsm[t] = prt[oc];
        __syncthreads();
        for (int s = 64; s > 0; s >>= 1) { if (t < s) wsm[t] += wsm[t + s]; __syncthreads(); }
        if (t == 0) g_hmp[(band * BSZ + b) * HID + ocg * 4 + oc] = wsm[0] * (1.0f / (float)NPIX);
        __syncthreads();
    }
}

// ---------------------------------------------------------------------------
// 4) FiLM parameter GEMVs (sums 6 conv2 band partials)
// ---------------------------------------------------------------------------
struct FilmArgs { const float* w[6]; const float* b[6]; };

__global__ void k_film(FilmArgs fa) {
    int s = blockIdx.x, b = blockIdx.y, o = threadIdx.x;
    __shared__ float sh[HID];
    if (threadIdx.x < HID) {
        int h = threadIdx.x;
        float acc = 0.f;
#pragma unroll
        for (int bd = 0; bd < 6; bd++) acc += g_hmp[(bd * BSZ + b) * HID + h];
        sh[h] = acc;
    }
    __syncthreads();
    const float* W = fa.w[s] + o * HID;
    float acc = fa.b[s][o];
#pragma unroll 8
    for (int h = 0; h < HID; h++) acc += sh[h] * W[h];
    g_film[(b * 6 + s) * 256 + o] = acc;
}

// ---------------------------------------------------------------------------
// 5) QKV GEMM via tf32 mma (+ bias + FiLM)
// ---------------------------------------------------------------------------
#define AW_STRIDE 36
#define BX_STRIDE 72

__global__ __launch_bounds__(256) void k_qkv(const float* __restrict__ bq,
                                             const float* __restrict__ bk,
                                             const float* __restrict__ bv) {
    __shared__ float wsm[128 * AW_STRIDE];
    __shared__ float xsm[32 * BX_STRIDE];
    int ntb = blockIdx.x, mt = blockIdx.y, z = blockIdx.z;
    int pr = z >> 2, b = z & 3;
    int t = threadIdx.x, warp = t >> 5, lane = t & 31;
    int gid = lane >> 2, tig = lane & 3;
    int n0 = ntb * 64;

    const float* W = g_Wt + pr * 65536 + mt * 128 * 256;
    const float* xb = g_xt + (size_t)b * CCH * NPIX;

    float s[8][4];
#pragma unroll
    for (int i = 0; i < 8; i++)
#pragma unroll
        for (int j = 0; j < 4; j++) s[i][j] = 0.f;

    for (int kk = 0; kk < 256; kk += 32) {
        if (kk) __syncthreads();
#pragma unroll
        for (int j = 0; j < 4; j++) {
            int idx = t + j * 256;
            int o = idx >> 3, cg = idx & 7;
            *(float4*)&wsm[o * AW_STRIDE + cg * 4] = *(const float4*)&W[o * 256 + kk + cg * 4];
        }
#pragma unroll
        for (int j = 0; j < 2; j++) {
            int idx = t + j * 256;
            int c = idx >> 4, ng = idx & 15;
            *(float4*)&xsm[c * BX_STRIDE + ng * 4] =
                *(const float4*)&xb[(size_t)(kk + c) * NPIX + n0 + ng * 4];
        }
        __syncthreads();
#pragma unroll
        for (int ks = 0; ks < 4; ks++) {
            uint32_t a[4];
            int ab = (warp * 16 + gid) * AW_STRIDE + ks * 8 + tig;
            a[0] = __float_as_uint(wsm[ab]);
            a[1] = __float_as_uint(wsm[ab + 8 * AW_STRIDE]);
            a[2] = __float_as_uint(wsm[ab + 4]);
            a[3] = __float_as_uint(wsm[ab + 8 * AW_STRIDE + 4]);
#pragma unroll
            for (int nt = 0; nt < 8; nt++) {
                int bbx = (ks * 8 + tig) * BX_STRIDE + nt * 8 + gid;
                mma_tf32(s[nt], a, __float_as_uint(xsm[bbx]),
                         __float_as_uint(xsm[bbx + 4 * BX_STRIDE]));
            }
        }
    }
    int o0 = mt * 128 + warp * 16 + gid, o1 = o0 + 8;
    const float* fg  = g_film + (b * 6 + 2 * pr) * 256;
    const float* fb2 = g_film + (b * 6 + 2 * pr + 1) * 256;
    const float* bias = (pr == 0) ? bq : (pr == 1) ? bk : bv;
    float g0 = fg[o0], g1 = fg[o1], e0 = fb2[o0], e1 = fb2[o1];
    float i0 = bias[o0], i1 = bias[o1];
    int h0 = o0 >> 5, d0 = o0 & 31, h1 = o1 >> 5, d1 = o1 & 31;
    float* outb = g_qkv + (size_t)pr * PR_STRIDE + (size_t)b * B_STRIDE;
    bool rnd = (pr != 0);
#pragma unroll
    for (int nt = 0; nt < 8; nt++) {
        int n = n0 + nt * 8 + 2 * tig;
        float v00 = g0 * (s[nt][0] + i0) + e0;
        float v01 = g0 * (s[nt][1] + i0) + e0;
        float v10 = g1 * (s[nt][2] + i1) + e1;
        float v11 = g1 * (s[nt][3] + i1) + e1;
        if (rnd) { v00 = tf32f(v00); v01 = tf32f(v01); v10 = tf32f(v10); v11 = tf32f(v11); }
        outb[((size_t)h0 * NPIX + n) * 32 + d0]     = v00;
        outb[((size_t)h0 * NPIX + n + 1) * 32 + d0] = v01;
        outb[((size_t)h1 * NPIX + n) * 32 + d1]     = v10;
        outb[((size_t)h1 * NPIX + n + 1) * 32 + d1] = v11;
    }
}

// ---------------------------------------------------------------------------
// 6) Flash attention with tf32 mma (K/V pre-rounded by k_qkv).
// ---------------------------------------------------------------------------
#define KS_STRIDE 36
#define VS_STRIDE 40
#define PS_STRIDE 68
#define ATTN_SMEM ((64 * KS_STRIDE + 64 * VS_STRIDE + 8 * 16 * PS_STRIDE + 64) * 4)

__global__ __launch_bounds__(256) void k_attn() {
    extern __shared__ float smp[];
    float* ksm = smp;
    float* vsm = ksm + 64 * KS_STRIDE;
    float* psm = vsm + 64 * VS_STRIDE;
    float* bsm = psm + 8 * 16 * PS_STRIDE;

    int t = threadIdx.x;
    int warp = t >> 5, lane = t & 31;
    int gid = lane >> 2, tig = lane & 3;
    int bh = blockIdx.y;
    int b = bh >> 3;

    const float* Qb = g_qkv + (size_t)bh * BH_STRIDE;
    const float* Kb = g_qkv + (size_t)PR_STRIDE + (size_t)bh * BH_STRIDE;
    const float* Vb = g_qkv + (size_t)2 * PR_STRIDE + (size_t)bh * BH_STRIDE;
    const float* bE = g_biasE + b * NPIX;

    int qr = blockIdx.x * 128 + warp * 16 + gid;

    uint32_t aq[4][4];
#pragma unroll
    for (int ks = 0; ks < 4; ks++) {
        aq[ks][0] = tf32c(Qb[(size_t)qr * 32 + ks * 8 + tig] * QSC);
        aq[ks][1] = tf32c(Qb[(size_t)(qr + 8) * 32 + ks * 8 + tig] * QSC);
        aq[ks][2] = tf32c(Qb[(size_t)qr * 32 + ks * 8 + tig + 4] * QSC);
        aq[ks][3] = tf32c(Qb[(size_t)(qr + 8) * 32 + ks * 8 + tig + 4] * QSC);
    }

    float o[4][4];
#pragma unroll
    for (int i = 0; i < 4; i++)
#pragma unroll
        for (int j = 0; j < 4; j++) o[i][j] = 0.f;
    float m0 = -1e30f, m1 = -1e30f, l0 = 0.f, l1 = 0.f;

    float* pw = psm + warp * 16 * PS_STRIDE;

    for (int nk = 0; nk < 36; ++nk) {
        const float4* Kg = (const float4*)Kb + nk * 512;
        const float4* Vg = (const float4*)Vb + nk * 512;
#pragma unroll
        for (int i = t; i < 512; i += 256) {
            int key = i >> 3, dq = i & 7;
            *(float4*)&ksm[key * KS_STRIDE + dq * 4] = Kg[i];
            *(float4*)&vsm[key * VS_STRIDE + dq * 4] = Vg[i];
        }
        if (t < 64) bsm[t] = bE[nk * 64 + t];
        __syncthreads();

        float s[8][4];
#pragma unroll
        for (int nt = 0; nt < 8; nt++)
#pragma unroll
            for (int c = 0; c < 4; c++) s[nt][c] = 0.f;
#pragma unroll
        for (int ks = 0; ks < 4; ks++) {
#pragma unroll
            for (int nt = 0; nt < 8; nt++) {
                int kb = (nt * 8 + gid) * KS_STRIDE + ks * 8 + tig;
                uint32_t b0 = __float_as_uint(ksm[kb]);
                uint32_t b1 = __float_as_uint(ksm[kb + 4]);
                mma_tf32(s[nt], aq[ks], b0, b1);
            }
        }
        float mx0 = -1e30f, mx1 = -1e30f;
#pragma unroll
        for (int nt = 0; nt < 8; nt++) {
            float b0v = bsm[nt * 8 + 2 * tig];
            float b1v = bsm[nt * 8 + 2 * tig + 1];
            s[nt][0] += b0v; s[nt][1] += b1v;
            s[nt][2] += b0v; s[nt][3] += b1v;
            mx0 = fmaxf(mx0, fmaxf(s[nt][0], s[nt][1]));
            mx1 = fmaxf(mx1, fmaxf(s[nt][2], s[nt][3]));
        }
        mx0 = fmaxf(mx0, __shfl_xor_sync(0xffffffffu, mx0, 1));
        mx0 = fmaxf(mx0, __shfl_xor_sync(0xffffffffu, mx0, 2));
        mx1 = fmaxf(mx1, __shfl_xor_sync(0xffffffffu, mx1, 1));
        mx1 = fmaxf(mx1, __shfl_xor_sync(0xffffffffu, mx1, 2));

        float mn0 = fmaxf(m0, mx0), mn1 = fmaxf(m1, mx1);
        float c0 = ex2f(m0 - mn0), c1 = ex2f(m1 - mn1);
        m0 = mn0; m1 = mn1;

        float rs0 = 0.f, rs1 = 0.f;
#pragma unroll
        for (int nt = 0; nt < 8; nt++) {
            float p00 = ex2f(s[nt][0] - mn0);
            float p01 = ex2f(s[nt][1] - mn0);
            float p10 = ex2f(s[nt][2] - mn1);
            float p11 = ex2f(s[nt][3] - mn1);
            rs0 += p00 + p01; rs1 += p10 + p11;
            float2 lo, hi;
            lo.x = tf32f(p00); lo.y = tf32f(p01);
            hi.x = tf32f(p10); hi.y = tf32f(p11);
            *(float2*)&pw[gid * PS_STRIDE + nt * 8 + 2 * tig] = lo;
            *(float2*)&pw[(gid + 8) * PS_STRIDE + nt * 8 + 2 * tig] = hi;
        }
        rs0 += __shfl_xor_sync(0xffffffffu, rs0, 1);
        rs0 += __shfl_xor_sync(0xffffffffu, rs0, 2);
        rs1 += __shfl_xor_sync(0xffffffffu, rs1, 1);
        rs1 += __shfl_xor_sync(0xffffffffu, rs1, 2);
        l0 = l0 * c0 + rs0;
        l1 = l1 * c1 + rs1;
#pragma unroll
        for (int nt = 0; nt < 4; nt++) {
            o[nt][0] *= c0; o[nt][1] *= c0;
            o[nt][2] *= c1; o[nt][3] *= c1;
        }
        __syncwarp();

#pragma unroll
        for (int ks = 0; ks < 8; ks++) {
            uint32_t a[4];
            a[0] = __float_as_uint(pw[gid * PS_STRIDE + ks * 8 + tig]);
            a[1] = __float_as_uint(pw[(gid + 8) * PS_STRIDE + ks * 8 + tig]);
            a[2] = __float_as_uint(pw[gid * PS_STRIDE + ks * 8 + tig + 4]);
            a[3] = __float_as_uint(pw[(gid + 8) * PS_STRIDE + ks * 8 + tig + 4]);
#pragma unroll
            for (int nt = 0; nt < 4; nt++) {
                int vb = (ks * 8 + tig) * VS_STRIDE + nt * 8 + gid;
                uint32_t b0 = __float_as_uint(vsm[vb]);
                uint32_t b1 = __float_as_uint(vsm[vb + 4 * VS_STRIDE]);
                mma_tf32(o[nt], a, b0, b1);
            }
        }
        __syncthreads();
    }

    float i0 = 1.0f / l0, i1 = 1.0f / l1;
    float* AO = g_ao + (size_t)bh * BH_STRIDE;
#pragma unroll
    for (int nt = 0; nt < 4; nt++) {
        float2 lo = make_float2(tf32f(o[nt][0] * i0), tf32f(o[nt][1] * i0));
        float2 hi = make_float2(tf32f(o[nt][2] * i1), tf32f(o[nt][3] * i1));
        *(float2*)&AO[(size_t)qr * 32 + nt * 8 + 2 * tig] = lo;
        *(float2*)&AO[(size_t)(qr + 8) * 32 + nt * 8 + 2 * tig] = hi;
    }
}

// ---------------------------------------------------------------------------
// 7) Output projection via tf32 mma
// ---------------------------------------------------------------------------
__global__ __launch_bounds__(256) void k_proj(const float* __restrict__ bproj,
                                              float* __restrict__ out) {
    __shared__ float wsm[128 * AW_STRIDE];
    __shared__ float bsm2[32 * BX_STRIDE];
    int ntb = blockIdx.x, mt = blockIdx.y, b = blockIdx.z;
    int t = threadIdx.x, warp = t >> 5, lane = t & 31;
    int gid = lane >> 2, tig = lane & 3;
    int n0 = ntb * 64;

    const float* W = g_Wt + 3 * 65536 + mt * 128 * 256;
    const float* AOb = g_ao + (size_t)b * B_STRIDE;

    float s[8][4];
#pragma unroll
    for (int i = 0; i < 8; i++)
#pragma unroll
        for (int j = 0; j < 4; j++) s[i][j] = 0.f;

    for (int kk = 0; kk < 256; kk += 32) {
        if (kk) __syncthreads();
#pragma unroll
        for (int j = 0; j < 4; j++) {
            int idx = t + j * 256;
            int o = idx >> 3, cg = idx & 7;
            *(float4*)&wsm[o * AW_STRIDE + cg * 4] = *(const float4*)&W[o * 256 + kk + cg * 4];
        }
#pragma unroll
        for (int j = 0; j < 8; j++) {
            int idx = t + j * 256;
            int c = idx >> 6, ng = idx & 63;
            int o = kk + c;
            bsm2[c * BX_STRIDE + ng] =
                AOb[((size_t)(o >> 5) * NPIX + n0 + ng) * 32 + (o & 31)];
        }
        __syncthreads();
#pragma unroll
        for (int ks = 0; ks < 4; ks++) {
            uint32_t a[4];
            int ab = (warp * 16 + gid) * AW_STRIDE + ks * 8 + tig;
            a[0] = __float_as_uint(wsm[ab]);
            a[1] = __float_as_uint(wsm[ab + 8 * AW_STRIDE]);
            a[2] = __float_as_uint(wsm[ab + 4]);
            a[3] = __float_as_uint(wsm[ab + 8 * AW_STRIDE + 4]);
#pragma unroll
            for (int nt = 0; nt < 8; nt++) {
                int bbx = (ks * 8 + tig) * BX_STRIDE + nt * 8 + gid;
                mma_tf32(s[nt], a, __float_as_uint(bsm2[bbx]),
                         __float_as_uint(bsm2[bbx + 4 * BX_STRIDE]));
            }
        }
    }
    int o0 = mt * 128 + warp * 16 + gid, o1 = o0 + 8;
    float bp0 = bproj[o0], bp1 = bproj[o1];
#pragma unroll
    for (int nt = 0; nt < 8; nt++) {
        int n = n0 + nt * 8 + 2 * tig;
        *(float2*)&out[((size_t)(b * 256 + o0)) * NPIX + n] =
            make_float2(s[nt][0] + bp0, s[nt][1] + bp0);
        *(float2*)&out[((size_t)(b * 256 + o1)) * NPIX + n] =
            make_float2(s[nt][2] + bp1, s[nt][3] + bp1);
    }
}

// ---------------------------------------------------------------------------
// launch
// ---------------------------------------------------------------------------
extern "C" void kernel_launch(void* const* d_in, const int* in_sizes, int n_in,
                              void* d_out, int out_size) {
    const float* x     = (const float*)d_in[0];
    const float* rgb   = (const float*)d_in[1];
    const float* wq    = (const float*)d_in[2];
    const float* bq    = (const float*)d_in[3];
    const float* wk    = (const float*)d_in[4];
    const float* bk    = (const float*)d_in[5];
    const float* wv    = (const float*)d_in[6];
    const float* bv    = (const float*)d_in[7];
    const float* wproj = (const float*)d_in[8];
    const float* bproj = (const float*)d_in[9];
    const float* c1w   = (const float*)d_in[10];
    const float* c1b   = (const float*)d_in[11];
    const float* c2w   = (const float*)d_in[12];
    const float* c2b   = (const float*)d_in[13];
    const float* alpha = (const float*)d_in[26];

    FilmArgs fa;
    fa.w[0] = (const float*)d_in[14]; fa.b[0] = (const float*)d_in[15];
    fa.w[1] = (const float*)d_in[16]; fa.b[1] = (const float*)d_in[17];
    fa.w[2] = (const float*)d_in[18]; fa.b[2] = (const float*)d_in[19];
    fa.w[3] = (const float*)d_in[20]; fa.b[3] = (const float*)d_in[21];
    fa.w[4] = (const float*)d_in[22]; fa.b[4] = (const float*)d_in[23];
    fa.w[5] = (const float*)d_in[24]; fa.b[5] = (const float*)d_in[25];

    static bool attr_done = false;
    if (!attr_done) {
        cudaFuncSetAttribute(k_attn, cudaFuncAttributeMaxDynamicSharedMemorySize, ATTN_SMEM);
        attr_done = true;
    }

    k_prep<<<2560, 256>>>(wq, wk, wv, wproj, x);
    k_lumabias<<<BSZ, 256>>>(rgb, alpha);
    k_conv1<<<dim3(HID, BSZ), 256>>>(c1w, c1b);
    k_conv2mean<<<dim3(32, BSZ, 6), dim3(16, 8)>>>(c2w, c2b);
    k_film<<<dim3(6, BSZ), 256>>>(fa);
    k_qkv<<<dim3(36, 2, 12), 256>>>(bq, bk, bv);
    k_attn<<<dim3(18, 32), 256, ATTN_SMEM>>>();
    k_proj<<<dim3(36, 2, 4), 256>>>(bproj, (float*)d_out);
}

// round 12
// speedup vs baseline: 1.4442x; 1.0652x over previous
#include <cuda_runtime.h>
#include <cstdint>

// ---------------------------------------------------------------------------
// Problem constants
// ---------------------------------------------------------------------------
#define BSZ    4
#define CCH    256
#define HH     48
#define WW     48
#define NPIX   2304          // 48*48
#define HEADS  8
#define DH     32
#define INNER  256
#define HID    128
#define LOG2E  1.4426950408889634f
#define QSC    (0.17677669529663687f * 1.4426950408889634f)

// padded h1 plane: 50 rows x 52 cols (px (r,c) at (r+1, c+1)); row stride 208B (16B aligned)
#define PH_ROWS 50
#define PH_COLS 52
#define PH_PLANE (PH_ROWS * PH_COLS)   // 2600

// ---------------------------------------------------------------------------
// Scratch
// ---------------------------------------------------------------------------
__device__ float g_Wt[4 * 256 * 256];          // tf32 patterns: wq,wk,wv,wproj
__device__ float g_xt[BSZ * CCH * NPIX];       // tf32 patterns of x
__device__ float g_luma[BSZ * NPIX];
__device__ float g_biasE[BSZ * NPIX];
__device__ float g_h1p[BSZ * HID * PH_PLANE]; // zero-padded conv1 output
__device__ float g_hmp[6 * BSZ * HID];         // 6 band partials
__device__ float g_film[BSZ * 6 * 256];
__device__ float g_qkv[3 * BSZ * HEADS * NPIX * DH];   // [pr][b][h][n][d]; K,V tf32
__device__ float g_ao[BSZ * HEADS * NPIX * DH];        // tf32-rounded

#define PR_STRIDE (BSZ * HEADS * NPIX * DH)
#define BH_STRIDE (NPIX * DH)
#define B_STRIDE  (HEADS * NPIX * DH)

// ---------------------------------------------------------------------------
// Helpers
// ---------------------------------------------------------------------------
static __device__ __forceinline__ float2 ffma2(float2 a, float2 b, float2 c) {
    float2 d;
    asm("fma.rn.f32x2 %0, %1, %2, %3;"
        : "=l"(reinterpret_cast<unsigned long long&>(d))
        : "l"(reinterpret_cast<unsigned long long&>(a)),
          "l"(reinterpret_cast<unsigned long long&>(b)),
          "l"(reinterpret_cast<unsigned long long&>(c)));
    return d;
}
static __device__ __forceinline__ float ex2f(float x) {
    float r;
    asm("ex2.approx.f32 %0, %1;" : "=f"(r) : "f"(x));
    return r;
}
static __device__ __forceinline__ uint32_t tf32c(float f) {
    uint32_t u;
    asm("cvt.rna.tf32.f32 %0, %1;" : "=r"(u) : "f"(f));
    return u;
}
static __device__ __forceinline__ float tf32f(float f) {
    return __uint_as_float(tf32c(f));
}
static __device__ __forceinline__ void mma_tf32(float* d, const uint32_t* a,
                                                uint32_t b0, uint32_t b1) {
    asm("mma.sync.aligned.m16n8k8.row.col.f32.tf32.tf32.f32 "
        "{%0,%1,%2,%3}, {%4,%5,%6,%7}, {%8,%9}, {%0,%1,%2,%3};"
        : "+f"(d[0]), "+f"(d[1]), "+f"(d[2]), "+f"(d[3])
        : "r"(a[0]), "r"(a[1]), "r"(a[2]), "r"(a[3]), "r"(b0), "r"(b1));
}

// ---------------------------------------------------------------------------
// 0) Prep: convert weights + x to tf32 bit patterns (layouts unchanged).
// ---------------------------------------------------------------------------
__global__ void k_prep(const float* __restrict__ wq, const float* __restrict__ wk,
                       const float* __restrict__ wv, const float* __restrict__ wp,
                       const float* __restrict__ x) {
    int i = blockIdx.x * 256 + threadIdx.x;
    float4 v, c;
    if (i < 65536) {
        int slot = i >> 14, j = i & 16383;
        const float* src = (slot == 0) ? wq : (slot == 1) ? wk : (slot == 2) ? wv : wp;
        v = ((const float4*)src)[j];
        c.x = tf32f(v.x); c.y = tf32f(v.y); c.z = tf32f(v.z); c.w = tf32f(v.w);
        ((float4*)g_Wt)[slot * 16384 + j] = c;
    } else {
        int j = i - 65536;
        v = ((const float4*)x)[j];
        c.x = tf32f(v.x); c.y = tf32f(v.y); c.z = tf32f(v.z); c.w = tf32f(v.w);
        ((float4*)g_xt)[j] = c;
    }
}

// ---------------------------------------------------------------------------
// 1) Luma + key bias, fused
// ---------------------------------------------------------------------------
__global__ void k_lumabias(const float* __restrict__ rgb, const float* __restrict__ alpha_p) {
    __shared__ float sy[NPIX];
    __shared__ float pli[2500];
    __shared__ float red[256];
    int b = blockIdx.x, t = threadIdx.x;
    const float* rp = rgb + (size_t)b * 3 * NPIX;
    float lmn = 1e30f, lmx = -1e30f;
#pragma unroll
    for (int k = 0; k < 9; k++) {
        int p = t + k * 256;
        float y = 0.299f * rp[p] + 0.587f * rp[NPIX + p] + 0.114f * rp[2 * NPIX + p];
        sy[p] = y;
        lmn = fminf(lmn, y); lmx = fmaxf(lmx, y);
    }
    red[t] = lmn; __syncthreads();
    for (int s = 128; s > 0; s >>= 1) { if (t < s) red[t] = fminf(red[t], red[t + s]); __syncthreads(); }
    float mn = red[0]; __syncthreads();
    red[t] = lmx; __syncthreads();
    for (int s = 128; s > 0; s >>= 1) { if (t < s) red[t] = fmaxf(red[t], red[t + s]); __syncthreads(); }
    float mx = red[0]; __syncthreads();
    float inv = 1.0f / (mx - mn + 1e-6f);

    for (int i = t; i < 2500; i += 256) pli[i] = 0.f;
    __syncthreads();
#pragma unroll
    for (int k = 0; k < 9; k++) {
        int p = t + k * 256;
        float ln = (sy[p] - mn) * inv;
        g_luma[b * NPIX + p] = ln;
        pli[(p / 48 + 1) * 50 + (p % 48) + 1] = 1.0f - ln;
    }
    __syncthreads();
    float lsum = 0.f;
#pragma unroll
    for (int k = 0; k < 9; k++) {
        int p = t + k * 256;
        int bi = (p / 48 + 1) * 50 + (p % 48) + 1;
        float s = pli[bi - 51] + pli[bi - 50] + pli[bi - 49]
                + pli[bi - 1]  + pli[bi]      + pli[bi + 1]
                + pli[bi + 49] + pli[bi + 50] + pli[bi + 51];
        s *= (1.0f / 9.0f);
        sy[p] = s; lsum += s;
    }
    red[t] = lsum; __syncthreads();
    for (int s = 128; s > 0; s >>= 1) { if (t < s) red[t] += red[t + s]; __syncthreads(); }
    float mean = red[0] * (1.0f / (float)NPIX);
    float a = *alpha_p;
#pragma unroll
    for (int k = 0; k < 9; k++) {
        int p = t + k * 256;
        g_biasE[b * NPIX + p] = a * (sy[p] - mean) * LOG2E;
    }
}

// ---------------------------------------------------------------------------
// 2) Conv1: luma[1ch] -> h1 padded [50x52] planes, 3x3 SAME, ReLU
// ---------------------------------------------------------------------------
__global__ void k_conv1(const float* __restrict__ w1, const float* __restrict__ b1) {
    __shared__ float pl[2500];
    int oc = blockIdx.x, b = blockIdx.y, t = threadIdx.x;
    for (int i = t; i < 2500; i += 256) pl[i] = 0.f;
    __syncthreads();
    const float* L = g_luma + b * NPIX;
#pragma unroll
    for (int k = 0; k < 9; k++) {
        int p = t + k * 256;
        pl[(p / 48 + 1) * 50 + (p % 48) + 1] = L[p];
    }
    __syncthreads();
    float w[9];
#pragma unroll
    for (int i = 0; i < 9; i++) w[i] = w1[oc * 9 + i];
    float bb = b1[oc];
    float* dst = g_h1p + ((size_t)(b * HID + oc)) * PH_PLANE;
    // zero the padded border cells (rows 0/49, col 0, cols 49..51)
    for (int i = t; i < PH_PLANE; i += 256) {
        int r = i / PH_COLS, c = i % PH_COLS;
        if (r == 0 || r == 49 || c == 0 || c >= 49) dst[i] = 0.f;
    }
#pragma unroll
    for (int k = 0; k < 9; k++) {
        int p = t + k * 256;
        int bi = (p / 48 + 1) * 50 + (p % 48) + 1;
        float s = bb
            + pl[bi - 51] * w[0] + pl[bi - 50] * w[1] + pl[bi - 49] * w[2]
            + pl[bi - 1]  * w[3] + pl[bi]      * w[4] + pl[bi + 1]  * w[5]
            + pl[bi + 49] * w[6] + pl[bi + 50] * w[7] + pl[bi + 51] * w[8];
        dst[(p / 48 + 1) * PH_COLS + (p % 48) + 1] = fmaxf(s, 0.f);
    }
}

// ---------------------------------------------------------------------------
// 3) Conv2 + ReLU + spatial mean (band partials). Padded h1: no shfl, no
//    bounds checks, no dead lanes. grid (32 ocg, 4 b, 6 band), 96 thr (12x8).
// ---------------------------------------------------------------------------
__global__ __launch_bounds__(96) void k_conv2mean(const float* __restrict__ w2,
                                                  const float* __restrict__ b2) {
    __shared__ float wsm[128 * 36];   // [ic][tap][oc4]
    int ocg = blockIdx.x, b = blockIdx.y, band = blockIdx.z;
    int t = threadIdx.x;
    int ty = t / 12, tx = t % 12;

    for (int i = t; i < 128 * 36; i += 96) {
        int ic = i / 36, r = i % 36;
        int tap = r >> 2, oc = r & 3;
        wsm[i] = w2[(((ocg * 4 + oc) * 128) + ic) * 9 + tap];
    }
    __syncthreads();

    int row = band * 8 + ty;          // px row
    int col0 = tx * 4;                // px col group; padded cols col0..col0+5
    const float* srcb = g_h1p + (size_t)b * HID * PH_PLANE;
    int off0 = row * PH_COLS + col0;  // padded row index = px row (row-1+1)

    float2 acc2[4][2];
#pragma unroll
    for (int j = 0; j < 4; j++) { acc2[j][0] = make_float2(0.f, 0.f); acc2[j][1] = make_float2(0.f, 0.f); }

    // preload ic = 0
    float4 ha[3]; float2 hb[3];
#pragma unroll
    for (int r = 0; r < 3; r++) {
        ha[r] = *(const float4*)&srcb[off0 + r * PH_COLS];
        hb[r] = *(const float2*)&srcb[off0 + r * PH_COLS + 4];
    }

    for (int ic = 0; ic < 128; ++ic) {
        float4 han[3]; float2 hbn[3];
        if (ic < 127) {
            const float* sn = srcb + (size_t)(ic + 1) * PH_PLANE;
#pragma unroll
            for (int r = 0; r < 3; r++) {
                han[r] = *(const float4*)&sn[off0 + r * PH_COLS];
                hbn[r] = *(const float2*)&sn[off0 + r * PH_COLS + 4];
            }
        }
        const float4* wv = (const float4*)&wsm[ic * 36];
#pragma unroll
        for (int r = 0; r < 3; r++) {
            float v[6] = { ha[r].x, ha[r].y, ha[r].z, ha[r].w, hb[r].x, hb[r].y };
#pragma unroll
            for (int tc = 0; tc < 3; tc++) {
                float4 w4 = wv[r * 3 + tc];
                float2 wlo = make_float2(w4.x, w4.y), whi = make_float2(w4.z, w4.w);
#pragma unroll
                for (int j = 0; j < 4; j++) {
                    float vv = v[j + tc];
                    float2 tt = make_float2(vv, vv);
                    acc2[j][0] = ffma2(tt, wlo, acc2[j][0]);
                    acc2[j][1] = ffma2(tt, whi, acc2[j][1]);
                }
            }
        }
#pragma unroll
        for (int r = 0; r < 3; r++) { ha[r] = han[r]; hb[r] = hbn[r]; }
    }
    float bb[4] = { b2[ocg * 4 + 0], b2[ocg * 4 + 1], b2[ocg * 4 + 2], b2[ocg * 4 + 3] };
    float prt[4];
#pragma unroll
    for (int oc = 0; oc < 4; oc++) prt[oc] = 0.f;
#pragma unroll
    for (int j = 0; j < 4; j++) {
        prt[0] += fmaxf(acc2[j][0].x + bb[0], 0.f);
        prt[1] += fmaxf(acc2[j][0].y + bb[1], 0.f);
        prt[2] += fmaxf(acc2[j][1].x + bb[2], 0.f);
        prt[3] += fmaxf(acc2[j][1].y + bb[3], 0.f);
    }
    __syncthreads();   // wsm reuse as reduction buffer
    for (int oc = 0; oc < 4; oc++) {
        wsm[t] = prt[oc];
        __syncthreads();
        if (t < 32) {
            float v = wsm[t] + wsm[t + 32] + wsm[t + 64];
            v += __shfl_xor_sync(0xffffffffu, v, 16);
            v += __shfl_xor_sync(0xffffffffu, v, 8);
            v += __shfl_xor_sync(0xffffffffu, v, 4);
            v += __shfl_xor_sync(0xffffffffu, v, 2);
            v += __shfl_xor_sync(0xffffffffu, v, 1);
            if (t == 0) g_hmp[(band * BSZ + b) * HID + ocg * 4 + oc] = v * (1.0f / (float)NPIX);
        }
        __syncthreads();
    }
}

// ---------------------------------------------------------------------------
// 4) FiLM parameter GEMVs (sums 6 conv2 band partials)
// ---------------------------------------------------------------------------
struct FilmArgs { const float* w[6]; const float* b[6]; };

__global__ void k_film(FilmArgs fa) {
    int s = blockIdx.x, b = blockIdx.y, o = threadIdx.x;
    __shared__ float sh[HID];
    if (threadIdx.x < HID) {
        int h = threadIdx.x;
        float acc = 0.f;
#pragma unroll
        for (int bd = 0; bd < 6; bd++) acc += g_hmp[(bd * BSZ + b) * HID + h];
        sh[h] = acc;
    }
    __syncthreads();
    const float* W = fa.w[s] + o * HID;
    float acc = fa.b[s][o];
#pragma unroll 8
    for (int h = 0; h < HID; h++) acc += sh[h] * W[h];
    g_film[(b * 6 + s) * 256 + o] = acc;
}

// ---------------------------------------------------------------------------
// 5) QKV GEMM via tf32 mma (+ bias + FiLM)
// ---------------------------------------------------------------------------
#define AW_STRIDE 36
#define BX_STRIDE 72

__global__ __launch_bounds__(256) void k_qkv(const float* __restrict__ bq,
                                             const float* __restrict__ bk,
                                             const float* __restrict__ bv) {
    __shared__ float wsm[128 * AW_STRIDE];
    __shared__ float xsm[32 * BX_STRIDE];
    int ntb = blockIdx.x, mt = blockIdx.y, z = blockIdx.z;
    int pr = z >> 2, b = z & 3;
    int t = threadIdx.x, warp = t >> 5, lane = t & 31;
    int gid = lane >> 2, tig = lane & 3;
    int n0 = ntb * 64;

    const float* W = g_Wt + pr * 65536 + mt * 128 * 256;
    const float* xb = g_xt + (size_t)b * CCH * NPIX;

    float s[8][4];
#pragma unroll
    for (int i = 0; i < 8; i++)
#pragma unroll
        for (int j = 0; j < 4; j++) s[i][j] = 0.f;

    for (int kk = 0; kk < 256; kk += 32) {
        if (kk) __syncthreads();
#pragma unroll
        for (int j = 0; j < 4; j++) {
            int idx = t + j * 256;
            int o = idx >> 3, cg = idx & 7;
            *(float4*)&wsm[o * AW_STRIDE + cg * 4] = *(const float4*)&W[o * 256 + kk + cg * 4];
        }
#pragma unroll
        for (int j = 0; j < 2; j++) {
            int idx = t + j * 256;
            int c = idx >> 4, ng = idx & 15;
            *(float4*)&xsm[c * BX_STRIDE + ng * 4] =
                *(const float4*)&xb[(size_t)(kk + c) * NPIX + n0 + ng * 4];
        }
        __syncthreads();
#pragma unroll
        for (int ks = 0; ks < 4; ks++) {
            uint32_t a[4];
            int ab = (warp * 16 + gid) * AW_STRIDE + ks * 8 + tig;
            a[0] = __float_as_uint(wsm[ab]);
            a[1] = __float_as_uint(wsm[ab + 8 * AW_STRIDE]);
            a[2] = __float_as_uint(wsm[ab + 4]);
            a[3] = __float_as_uint(wsm[ab + 8 * AW_STRIDE + 4]);
#pragma unroll
            for (int nt = 0; nt < 8; nt++) {
                int bbx = (ks * 8 + tig) * BX_STRIDE + nt * 8 + gid;
                mma_tf32(s[nt], a, __float_as_uint(xsm[bbx]),
                         __float_as_uint(xsm[bbx + 4 * BX_STRIDE]));
            }
        }
    }
    int o0 = mt * 128 + warp * 16 + gid, o1 = o0 + 8;
    const float* fg  = g_film + (b * 6 + 2 * pr) * 256;
    const float* fb2 = g_film + (b * 6 + 2 * pr + 1) * 256;
    const float* bias = (pr == 0) ? bq : (pr == 1) ? bk : bv;
    float g0 = fg[o0], g1 = fg[o1], e0 = fb2[o0], e1 = fb2[o1];
    float i0 = bias[o0], i1 = bias[o1];
    int h0 = o0 >> 5, d0 = o0 & 31, h1 = o1 >> 5, d1 = o1 & 31;
    float* outb = g_qkv + (size_t)pr * PR_STRIDE + (size_t)b * B_STRIDE;
    bool rnd = (pr != 0);
#pragma unroll
    for (int nt = 0; nt < 8; nt++) {
        int n = n0 + nt * 8 + 2 * tig;
        float v00 = g0 * (s[nt][0] + i0) + e0;
        float v01 = g0 * (s[nt][1] + i0) + e0;
        float v10 = g1 * (s[nt][2] + i1) + e1;
        float v11 = g1 * (s[nt][3] + i1) + e1;
        if (rnd) { v00 = tf32f(v00); v01 = tf32f(v01); v10 = tf32f(v10); v11 = tf32f(v11); }
        outb[((size_t)h0 * NPIX + n) * 32 + d0]     = v00;
        outb[((size_t)h0 * NPIX + n + 1) * 32 + d0] = v01;
        outb[((size_t)h1 * NPIX + n) * 32 + d1]     = v10;
        outb[((size_t)h1 * NPIX + n + 1) * 32 + d1] = v11;
    }
}

// ---------------------------------------------------------------------------
// 6) Flash attention with tf32 mma (K/V pre-rounded by k_qkv).
// ---------------------------------------------------------------------------
#define KS_STRIDE 36
#define VS_STRIDE 40
#define PS_STRIDE 68
#define ATTN_SMEM ((64 * KS_STRIDE + 64 * VS_STRIDE + 8 * 16 * PS_STRIDE + 64) * 4)

__global__ __launch_bounds__(256) void k_attn() {
    extern __shared__ float smp[];
    float* ksm = smp;
    float* vsm = ksm + 64 * KS_STRIDE;
    float* psm = vsm + 64 * VS_STRIDE;
    float* bsm = psm + 8 * 16 * PS_STRIDE;

    int t = threadIdx.x;
    int warp = t >> 5, lane = t & 31;
    int gid = lane >> 2, tig = lane & 3;
    int bh = blockIdx.y;
    int b = bh >> 3;

    const float* Qb = g_qkv + (size_t)bh * BH_STRIDE;
    const float* Kb = g_qkv + (size_t)PR_STRIDE + (size_t)bh * BH_STRIDE;
    const float* Vb = g_qkv + (size_t)2 * PR_STRIDE + (size_t)bh * BH_STRIDE;
    const float* bE = g_biasE + b * NPIX;

    int qr = blockIdx.x * 128 + warp * 16 + gid;

    uint32_t aq[4][4];
#pragma unroll
    for (int ks = 0; ks < 4; ks++) {
        aq[ks][0] = tf32c(Qb[(size_t)qr * 32 + ks * 8 + tig] * QSC);
        aq[ks][1] = tf32c(Qb[(size_t)(qr + 8) * 32 + ks * 8 + tig] * QSC);
        aq[ks][2] = tf32c(Qb[(size_t)qr * 32 + ks * 8 + tig + 4] * QSC);
        aq[ks][3] = tf32c(Qb[(size_t)(qr + 8) * 32 + ks * 8 + tig + 4] * QSC);
    }

    float o[4][4];
#pragma unroll
    for (int i = 0; i < 4; i++)
#pragma unroll
        for (int j = 0; j < 4; j++) o[i][j] = 0.f;
    float m0 = -1e30f, m1 = -1e30f, l0 = 0.f, l1 = 0.f;

    float* pw = psm + warp * 16 * PS_STRIDE;

    for (int nk = 0; nk < 36; ++nk) {
        const float4* Kg = (const float4*)Kb + nk * 512;
        const float4* Vg = (const float4*)Vb + nk * 512;
#pragma unroll
        for (int i = t; i < 512; i += 256) {
            int key = i >> 3, dq = i & 7;
            *(float4*)&ksm[key * KS_STRIDE + dq * 4] = Kg[i];
            *(float4*)&vsm[key * VS_STRIDE + dq * 4] = Vg[i];
        }
        if (t < 64) bsm[t] = bE[nk * 64 + t];
        __syncthreads();

        float s[8][4];
#pragma unroll
        for (int nt = 0; nt < 8; nt++)
#pragma unroll
            for (int c = 0; c < 4; c++) s[nt][c] = 0.f;
#pragma unroll
        for (int ks = 0; ks < 4; ks++) {
#pragma unroll
            for (int nt = 0; nt < 8; nt++) {
                int kb = (nt * 8 + gid) * KS_STRIDE + ks * 8 + tig;
                uint32_t b0 = __float_as_uint(ksm[kb]);
                uint32_t b1 = __float_as_uint(ksm[kb + 4]);
                mma_tf32(s[nt], aq[ks], b0, b1);
            }
        }
        float mx0 = -1e30f, mx1 = -1e30f;
#pragma unroll
        for (int nt = 0; nt < 8; nt++) {
            float b0v = bsm[nt * 8 + 2 * tig];
            float b1v = bsm[nt * 8 + 2 * tig + 1];
            s[nt][0] += b0v; s[nt][1] += b1v;
            s[nt][2] += b0v; s[nt][3] += b1v;
            mx0 = fmaxf(mx0, fmaxf(s[nt][0], s[nt][1]));
            mx1 = fmaxf(mx1, fmaxf(s[nt][2], s[nt][3]));
        }
        mx0 = fmaxf(mx0, __shfl_xor_sync(0xffffffffu, mx0, 1));
        mx0 = fmaxf(mx0, __shfl_xor_sync(0xffffffffu, mx0, 2));
        mx1 = fmaxf(mx1, __shfl_xor_sync(0xffffffffu, mx1, 1));
        mx1 = fmaxf(mx1, __shfl_xor_sync(0xffffffffu, mx1, 2));

        float mn0 = fmaxf(m0, mx0), mn1 = fmaxf(m1, mx1);
        float c0 = ex2f(m0 - mn0), c1 = ex2f(m1 - mn1);
        m0 = mn0; m1 = mn1;

        float rs0 = 0.f, rs1 = 0.f;
#pragma unroll
        for (int nt = 0; nt < 8; nt++) {
            float p00 = ex2f(s[nt][0] - mn0);
            float p01 = ex2f(s[nt][1] - mn0);
            float p10 = ex2f(s[nt][2] - mn1);
            float p11 = ex2f(s[nt][3] - mn1);
            rs0 += p00 + p01; rs1 += p10 + p11;
            float2 lo, hi;
            lo.x = tf32f(p00); lo.y = tf32f(p01);
            hi.x = tf32f(p10); hi.y = tf32f(p11);
            *(float2*)&pw[gid * PS_STRIDE + nt * 8 + 2 * tig] = lo;
            *(float2*)&pw[(gid + 8) * PS_STRIDE + nt * 8 + 2 * tig] = hi;
        }
        rs0 += __shfl_xor_sync(0xffffffffu, rs0, 1);
        rs0 += __shfl_xor_sync(0xffffffffu, rs0, 2);
        rs1 += __shfl_xor_sync(0xffffffffu, rs1, 1);
        rs1 += __shfl_xor_sync(0xffffffffu, rs1, 2);
        l0 = l0 * c0 + rs0;
        l1 = l1 * c1 + rs1;
#pragma unroll
        for (int nt = 0; nt < 4; nt++) {
            o[nt][0] *= c0; o[nt][1] *= c0;
            o[nt][2] *= c1; o[nt][3] *= c1;
        }
        __syncwarp();

#pragma unroll
        for (int ks = 0; ks < 8; ks++) {
            uint32_t a[4];
            a[0] = __float_as_uint(pw[gid * PS_STRIDE + ks * 8 + tig]);
            a[1] = __float_as_uint(pw[(gid + 8) * PS_STRIDE + ks * 8 + tig]);
            a[2] = __float_as_uint(pw[gid * PS_STRIDE + ks * 8 + tig + 4]);
            a[3] = __float_as_uint(pw[(gid + 8) * PS_STRIDE + ks * 8 + tig + 4]);
#pragma unroll
            for (int nt = 0; nt < 4; nt++) {
                int vb = (ks * 8 + tig) * VS_STRIDE + nt * 8 + gid;
                uint32_t b0 = __float_as_uint(vsm[vb]);
                uint32_t b1 = __float_as_uint(vsm[vb + 4 * VS_STRIDE]);
                mma_tf32(o[nt], a, b0, b1);
            }
        }
        __syncthreads();
    }

    float i0 = 1.0f / l0, i1 = 1.0f / l1;
    float* AO = g_ao + (size_t)bh * BH_STRIDE;
#pragma unroll
    for (int nt = 0; nt < 4; nt++) {
        float2 lo = make_float2(tf32f(o[nt][0] * i0), tf32f(o[nt][1] * i0));
        float2 hi = make_float2(tf32f(o[nt][2] * i1), tf32f(o[nt][3] * i1));
        *(float2*)&AO[(size_t)qr * 32 + nt * 8 + 2 * tig] = lo;
        *(float2*)&AO[(size_t)(qr + 8) * 32 + nt * 8 + 2 * tig] = hi;
    }
}

// ---------------------------------------------------------------------------
// 7) Output projection via tf32 mma
// ---------------------------------------------------------------------------
__global__ __launch_bounds__(256) void k_proj(const float* __restrict__ bproj,
                                              float* __restrict__ out) {
    __shared__ float wsm[128 * AW_STRIDE];
    __shared__ float bsm2[32 * BX_STRIDE];
    int ntb = blockIdx.x, mt = blockIdx.y, b = blockIdx.z;
    int t = threadIdx.x, warp = t >> 5, lane = t & 31;
    int gid = lane >> 2, tig = lane & 3;
    int n0 = ntb * 64;

    const float* W = g_Wt + 3 * 65536 + mt * 128 * 256;
    const float* AOb = g_ao + (size_t)b * B_STRIDE;

    float s[8][4];
#pragma unroll
    for (int i = 0; i < 8; i++)
#pragma unroll
        for (int j = 0; j < 4; j++) s[i][j] = 0.f;

    for (int kk = 0; kk < 256; kk += 32) {
        if (kk) __syncthreads();
#pragma unroll
        for (int j = 0; j < 4; j++) {
            int idx = t + j * 256;
            int o = idx >> 3, cg = idx & 7;
            *(float4*)&wsm[o * AW_STRIDE + cg * 4] = *(const float4*)&W[o * 256 + kk + cg * 4];
        }
#pragma unroll
        for (int j = 0; j < 8; j++) {
            int idx = t + j * 256;
            int c = idx >> 6, ng = idx & 63;
            int o = kk + c;
            bsm2[c * BX_STRIDE + ng] =
                AOb[((size_t)(o >> 5) * NPIX + n0 + ng) * 32 + (o & 31)];
        }
        __syncthreads();
#pragma unroll
        for (int ks = 0; ks < 4; ks++) {
            uint32_t a[4];
            int ab = (warp * 16 + gid) * AW_STRIDE + ks * 8 + tig;
            a[0] = __float_as_uint(wsm[ab]);
            a[1] = __float_as_uint(wsm[ab + 8 * AW_STRIDE]);
            a[2] = __float_as_uint(wsm[ab + 4]);
            a[3] = __float_as_uint(wsm[ab + 8 * AW_STRIDE + 4]);
#pragma unroll
            for (int nt = 0; nt < 8; nt++) {
                int bbx = (ks * 8 + tig) * BX_STRIDE + nt * 8 + gid;
                mma_tf32(s[nt], a, __float_as_uint(bsm2[bbx]),
                         __float_as_uint(bsm2[bbx + 4 * BX_STRIDE]));
            }
        }
    }
    int o0 = mt * 128 + warp * 16 + gid, o1 = o0 + 8;
    float bp0 = bproj[o0], bp1 = bproj[o1];
#pragma unroll
    for (int nt = 0; nt < 8; nt++) {
        int n = n0 + nt * 8 + 2 * tig;
        *(float2*)&out[((size_t)(b * 256 + o0)) * NPIX + n] =
            make_float2(s[nt][0] + bp0, s[nt][1] + bp0);
        *(float2*)&out[((size_t)(b * 256 + o1)) * NPIX + n] =
            make_float2(s[nt][2] + bp1, s[nt][3] + bp1);
    }
}

// ---------------------------------------------------------------------------
// launch
// ---------------------------------------------------------------------------
extern "C" void kernel_launch(void* const* d_in, const int* in_sizes, int n_in,
                              void* d_out, int out_size) {
    const float* x     = (const float*)d_in[0];
    const float* rgb   = (const float*)d_in[1];
    const float* wq    = (const float*)d_in[2];
    const float* bq    = (const float*)d_in[3];
    const float* wk    = (const float*)d_in[4];
    const float* bk    = (const float*)d_in[5];
    const float* wv    = (const float*)d_in[6];
    const float* bv    = (const float*)d_in[7];
    const float* wproj = (const float*)d_in[8];
    const float* bproj = (const float*)d_in[9];
    const float* c1w   = (const float*)d_in[10];
    const float* c1b   = (const float*)d_in[11];
    const float* c2w   = (const float*)d_in[12];
    const float* c2b   = (const float*)d_in[13];
    const float* alpha = (const float*)d_in[26];

    FilmArgs fa;
    fa.w[0] = (const float*)d_in[14]; fa.b[0] = (const float*)d_in[15];
    fa.w[1] = (const float*)d_in[16]; fa.b[1] = (const float*)d_in[17];
    fa.w[2] = (const float*)d_in[18]; fa.b[2] = (const float*)d_in[19];
    fa.w[3] = (const float*)d_in[20]; fa.b[3] = (const float*)d_in[21];
    fa.w[4] = (const float*)d_in[22]; fa.b[4] = (const float*)d_in[23];
    fa.w[5] = (const float*)d_in[24]; fa.b[5] = (const float*)d_in[25];

    static bool attr_done = false;
    if (!attr_done) {
        cudaFuncSetAttribute(k_attn, cudaFuncAttributeMaxDynamicSharedMemorySize, ATTN_SMEM);
        attr_done = true;
    }

    k_prep<<<2560, 256>>>(wq, wk, wv, wproj, x);
    k_lumabias<<<BSZ, 256>>>(rgb, alpha);
    k_conv1<<<dim3(HID, BSZ), 256>>>(c1w, c1b);
    k_conv2mean<<<dim3(32, BSZ, 6), 96>>>(c2w, c2b);
    k_film<<<dim3(6, BSZ), 256>>>(fa);
    k_qkv<<<dim3(36, 2, 12), 256>>>(bq, bk, bv);
    k_attn<<<dim3(18, 32), 256, ATTN_SMEM>>>();
    k_proj<<<dim3(36, 2, 4), 256>>>(bproj, (float*)d_out);
}

// round 13
// speedup vs baseline: 1.5005x; 1.0390x over previous
#include <cuda_runtime.h>
#include <cstdint>

// ---------------------------------------------------------------------------
// Problem constants
// ---------------------------------------------------------------------------
#define BSZ    4
#define CCH    256
#define HH     48
#define WW     48
#define NPIX   2304          // 48*48
#define HEADS  8
#define DH     32
#define INNER  256
#define HID    128
#define LOG2E  1.4426950408889634f
#define QSC    (0.17677669529663687f * 1.4426950408889634f)

// padded h1 plane: 50 rows x 52 cols (px (r,c) at (r+1, c+1))
#define PH_ROWS 50
#define PH_COLS 52
#define PH_PLANE (PH_ROWS * PH_COLS)   // 2600

// ---------------------------------------------------------------------------
// Scratch
// ---------------------------------------------------------------------------
__device__ float g_Wt[4 * 256 * 256];          // tf32 patterns: wq,wk,wv,wproj
__device__ float g_xt[BSZ * CCH * NPIX];       // tf32 patterns of x
__device__ float g_luma[BSZ * NPIX];
__device__ float g_biasE[BSZ * NPIX];
__device__ float g_h1p[BSZ * HID * PH_PLANE]; // zero-padded conv1 output
__device__ float g_hmp[6 * BSZ * HID];         // 6 band partials
__device__ float g_film[BSZ * 6 * 256];
__device__ float g_qkv[3 * BSZ * HEADS * NPIX * DH];   // [pr][b][h][n][d]; K,V tf32
__device__ float g_ao[BSZ * HEADS * NPIX * DH];        // tf32-rounded

#define PR_STRIDE (BSZ * HEADS * NPIX * DH)
#define BH_STRIDE (NPIX * DH)
#define B_STRIDE  (HEADS * NPIX * DH)

// ---------------------------------------------------------------------------
// Helpers
// ---------------------------------------------------------------------------
static __device__ __forceinline__ float2 ffma2(float2 a, float2 b, float2 c) {
    float2 d;
    asm("fma.rn.f32x2 %0, %1, %2, %3;"
        : "=l"(reinterpret_cast<unsigned long long&>(d))
        : "l"(reinterpret_cast<unsigned long long&>(a)),
          "l"(reinterpret_cast<unsigned long long&>(b)),
          "l"(reinterpret_cast<unsigned long long&>(c)));
    return d;
}
static __device__ __forceinline__ float ex2f(float x) {
    float r;
    asm("ex2.approx.f32 %0, %1;" : "=f"(r) : "f"(x));
    return r;
}
static __device__ __forceinline__ uint32_t tf32c(float f) {
    uint32_t u;
    asm("cvt.rna.tf32.f32 %0, %1;" : "=r"(u) : "f"(f));
    return u;
}
static __device__ __forceinline__ float tf32f(float f) {
    return __uint_as_float(tf32c(f));
}
static __device__ __forceinline__ void mma_tf32(float* d, const uint32_t* a,
                                                uint32_t b0, uint32_t b1) {
    asm("mma.sync.aligned.m16n8k8.row.col.f32.tf32.tf32.f32 "
        "{%0,%1,%2,%3}, {%4,%5,%6,%7}, {%8,%9}, {%0,%1,%2,%3};"
        : "+f"(d[0]), "+f"(d[1]), "+f"(d[2]), "+f"(d[3])
        : "r"(a[0]), "r"(a[1]), "r"(a[2]), "r"(a[3]), "r"(b0), "r"(b1));
}
static __device__ __forceinline__ void cpasync16(uint32_t smem_addr, const void* gptr) {
    asm volatile("cp.async.cg.shared.global [%0], [%1], 16;"
                 :: "r"(smem_addr), "l"(gptr));
}
#define CP_COMMIT() asm volatile("cp.async.commit_group;")
#define CP_WAIT0()  asm volatile("cp.async.wait_group 0;" ::: "memory")

// ---------------------------------------------------------------------------
// 0) Prep: convert weights + x to tf32 bit patterns (layouts unchanged).
// ---------------------------------------------------------------------------
__global__ void k_prep(const float* __restrict__ wq, const float* __restrict__ wk,
                       const float* __restrict__ wv, const float* __restrict__ wp,
                       const float* __restrict__ x) {
    int i = blockIdx.x * 256 + threadIdx.x;
    float4 v, c;
    if (i < 65536) {
        int slot = i >> 14, j = i & 16383;
        const float* src = (slot == 0) ? wq : (slot == 1) ? wk : (slot == 2) ? wv : wp;
        v = ((const float4*)src)[j];
        c.x = tf32f(v.x); c.y = tf32f(v.y); c.z = tf32f(v.z); c.w = tf32f(v.w);
        ((float4*)g_Wt)[slot * 16384 + j] = c;
    } else {
        int j = i - 65536;
        v = ((const float4*)x)[j];
        c.x = tf32f(v.x); c.y = tf32f(v.y); c.z = tf32f(v.z); c.w = tf32f(v.w);
        ((float4*)g_xt)[j] = c;
    }
}

// ---------------------------------------------------------------------------
// 1) Luma + key bias, fused
// ---------------------------------------------------------------------------
__global__ void k_lumabias(const float* __restrict__ rgb, const float* __restrict__ alpha_p) {
    __shared__ float sy[NPIX];
    __shared__ float pli[2500];
    __shared__ float red[256];
    int b = blockIdx.x, t = threadIdx.x;
    const float* rp = rgb + (size_t)b * 3 * NPIX;
    float lmn = 1e30f, lmx = -1e30f;
#pragma unroll
    for (int k = 0; k < 9; k++) {
        int p = t + k * 256;
        float y = 0.299f * rp[p] + 0.587f * rp[NPIX + p] + 0.114f * rp[2 * NPIX + p];
        sy[p] = y;
        lmn = fminf(lmn, y); lmx = fmaxf(lmx, y);
    }
    red[t] = lmn; __syncthreads();
    for (int s = 128; s > 0; s >>= 1) { if (t < s) red[t] = fminf(red[t], red[t + s]); __syncthreads(); }
    float mn = red[0]; __syncthreads();
    red[t] = lmx; __syncthreads();
    for (int s = 128; s > 0; s >>= 1) { if (t < s) red[t] = fmaxf(red[t], red[t + s]); __syncthreads(); }
    float mx = red[0]; __syncthreads();
    float inv = 1.0f / (mx - mn + 1e-6f);

    for (int i = t; i < 2500; i += 256) pli[i] = 0.f;
    __syncthreads();
#pragma unroll
    for (int k = 0; k < 9; k++) {
        int p = t + k * 256;
        float ln = (sy[p] - mn) * inv;
        g_luma[b * NPIX + p] = ln;
        pli[(p / 48 + 1) * 50 + (p % 48) + 1] = 1.0f - ln;
    }
    __syncthreads();
    float lsum = 0.f;
#pragma unroll
    for (int k = 0; k < 9; k++) {
        int p = t + k * 256;
        int bi = (p / 48 + 1) * 50 + (p % 48) + 1;
        float s = pli[bi - 51] + pli[bi - 50] + pli[bi - 49]
                + pli[bi - 1]  + pli[bi]      + pli[bi + 1]
                + pli[bi + 49] + pli[bi + 50] + pli[bi + 51];
        s *= (1.0f / 9.0f);
        sy[p] = s; lsum += s;
    }
    red[t] = lsum; __syncthreads();
    for (int s = 128; s > 0; s >>= 1) { if (t < s) red[t] += red[t + s]; __syncthreads(); }
    float mean = red[0] * (1.0f / (float)NPIX);
    float a = *alpha_p;
#pragma unroll
    for (int k = 0; k < 9; k++) {
        int p = t + k * 256;
        g_biasE[b * NPIX + p] = a * (sy[p] - mean) * LOG2E;
    }
}

// ---------------------------------------------------------------------------
// 2) Conv1: luma[1ch] -> h1 padded [50x52] planes, 3x3 SAME, ReLU
// ---------------------------------------------------------------------------
__global__ void k_conv1(const float* __restrict__ w1, const float* __restrict__ b1) {
    __shared__ float pl[2500];
    int oc = blockIdx.x, b = blockIdx.y, t = threadIdx.x;
    for (int i = t; i < 2500; i += 256) pl[i] = 0.f;
    __syncthreads();
    const float* L = g_luma + b * NPIX;
#pragma unroll
    for (int k = 0; k < 9; k++) {
        int p = t + k * 256;
        pl[(p / 48 + 1) * 50 + (p % 48) + 1] = L[p];
    }
    __syncthreads();
    float w[9];
#pragma unroll
    for (int i = 0; i < 9; i++) w[i] = w1[oc * 9 + i];
    float bb = b1[oc];
    float* dst = g_h1p + ((size_t)(b * HID + oc)) * PH_PLANE;
    for (int i = t; i < PH_PLANE; i += 256) {
        int r = i / PH_COLS, c = i % PH_COLS;
        if (r == 0 || r == 49 || c == 0 || c >= 49) dst[i] = 0.f;
    }
#pragma unroll
    for (int k = 0; k < 9; k++) {
        int p = t + k * 256;
        int bi = (p / 48 + 1) * 50 + (p % 48) + 1;
        float s = bb
            + pl[bi - 51] * w[0] + pl[bi - 50] * w[1] + pl[bi - 49] * w[2]
            + pl[bi - 1]  * w[3] + pl[bi]      * w[4] + pl[bi + 1]  * w[5]
            + pl[bi + 49] * w[6] + pl[bi + 50] * w[7] + pl[bi + 51] * w[8];
        dst[(p / 48 + 1) * PH_COLS + (p % 48) + 1] = fmaxf(s, 0.f);
    }
}

// ---------------------------------------------------------------------------
// 3) Conv2 + ReLU + spatial mean (band partials). Padded h1.
//    grid (32 ocg, 4 b, 6 band), 96 thr (12x8).
// ---------------------------------------------------------------------------
__global__ __launch_bounds__(96) void k_conv2mean(const float* __restrict__ w2,
                                                  const float* __restrict__ b2) {
    __shared__ float wsm[128 * 36];   // [ic][tap][oc4]
    int ocg = blockIdx.x, b = blockIdx.y, band = blockIdx.z;
    int t = threadIdx.x;
    int ty = t / 12, tx = t % 12;

    for (int i = t; i < 128 * 36; i += 96) {
        int ic = i / 36, r = i % 36;
        int tap = r >> 2, oc = r & 3;
        wsm[i] = w2[(((ocg * 4 + oc) * 128) + ic) * 9 + tap];
    }
    __syncthreads();

    int row = band * 8 + ty;
    int col0 = tx * 4;
    const float* srcb = g_h1p + (size_t)b * HID * PH_PLANE;
    int off0 = row * PH_COLS + col0;

    float2 acc2[4][2];
#pragma unroll
    for (int j = 0; j < 4; j++) { acc2[j][0] = make_float2(0.f, 0.f); acc2[j][1] = make_float2(0.f, 0.f); }

    float4 ha[3]; float2 hb[3];
#pragma unroll
    for (int r = 0; r < 3; r++) {
        ha[r] = *(const float4*)&srcb[off0 + r * PH_COLS];
        hb[r] = *(const float2*)&srcb[off0 + r * PH_COLS + 4];
    }

    for (int ic = 0; ic < 128; ++ic) {
        float4 han[3]; float2 hbn[3];
        if (ic < 127) {
            const float* sn = srcb + (size_t)(ic + 1) * PH_PLANE;
#pragma unroll
            for (int r = 0; r < 3; r++) {
                han[r] = *(const float4*)&sn[off0 + r * PH_COLS];
                hbn[r] = *(const float2*)&sn[off0 + r * PH_COLS + 4];
            }
        }
        const float4* wv = (const float4*)&wsm[ic * 36];
#pragma unroll
        for (int r = 0; r < 3; r++) {
            float v[6] = { ha[r].x, ha[r].y, ha[r].z, ha[r].w, hb[r].x, hb[r].y };
#pragma unroll
            for (int tc = 0; tc < 3; tc++) {
                float4 w4 = wv[r * 3 + tc];
                float2 wlo = make_float2(w4.x, w4.y), whi = make_float2(w4.z, w4.w);
#pragma unroll
                for (int j = 0; j < 4; j++) {
                    float vv = v[j + tc];
                    float2 tt = make_float2(vv, vv);
                    acc2[j][0] = ffma2(tt, wlo, acc2[j][0]);
                    acc2[j][1] = ffma2(tt, whi, acc2[j][1]);
                }
            }
        }
#pragma unroll
        for (int r = 0; r < 3; r++) { ha[r] = han[r]; hb[r] = hbn[r]; }
    }
    float bb[4] = { b2[ocg * 4 + 0], b2[ocg * 4 + 1], b2[ocg * 4 + 2], b2[ocg * 4 + 3] };
    float prt[4];
#pragma unroll
    for (int oc = 0; oc < 4; oc++) prt[oc] = 0.f;
#pragma unroll
    for (int j = 0; j < 4; j++) {
        prt[0] += fmaxf(acc2[j][0].x + bb[0], 0.f);
        prt[1] += fmaxf(acc2[j][0].y + bb[1], 0.f);
        prt[2] += fmaxf(acc2[j][1].x + bb[2], 0.f);
        prt[3] += fmaxf(acc2[j][1].y + bb[3], 0.f);
    }
    __syncthreads();
    for (int oc = 0; oc < 4; oc++) {
        wsm[t] = prt[oc];
        __syncthreads();
        if (t < 32) {
            float v = wsm[t] + wsm[t + 32] + wsm[t + 64];
            v += __shfl_xor_sync(0xffffffffu, v, 16);
            v += __shfl_xor_sync(0xffffffffu, v, 8);
            v += __shfl_xor_sync(0xffffffffu, v, 4);
            v += __shfl_xor_sync(0xffffffffu, v, 2);
            v += __shfl_xor_sync(0xffffffffu, v, 1);
            if (t == 0) g_hmp[(band * BSZ + b) * HID + ocg * 4 + oc] = v * (1.0f / (float)NPIX);
        }
        __syncthreads();
    }
}

// ---------------------------------------------------------------------------
// 4) FiLM parameter GEMVs (sums 6 conv2 band partials)
// ---------------------------------------------------------------------------
struct FilmArgs { const float* w[6]; const float* b[6]; };

__global__ void k_film(FilmArgs fa) {
    int s = blockIdx.x, b = blockIdx.y, o = threadIdx.x;
    __shared__ float sh[HID];
    if (threadIdx.x < HID) {
        int h = threadIdx.x;
        float acc = 0.f;
#pragma unroll
        for (int bd = 0; bd < 6; bd++) acc += g_hmp[(bd * BSZ + b) * HID + h];
        sh[h] = acc;
    }
    __syncthreads();
    const float* W = fa.w[s] + o * HID;
    float acc = fa.b[s][o];
#pragma unroll 8
    for (int h = 0; h < HID; h++) acc += sh[h] * W[h];
    g_film[(b * 6 + s) * 256 + o] = acc;
}

// ---------------------------------------------------------------------------
// 5) QKV GEMM via tf32 mma (+ bias + FiLM)
// ---------------------------------------------------------------------------
#define AW_STRIDE 36
#define BX_STRIDE 72

__global__ __launch_bounds__(256) void k_qkv(const float* __restrict__ bq,
                                             const float* __restrict__ bk,
                                             const float* __restrict__ bv) {
    __shared__ float wsm[128 * AW_STRIDE];
    __shared__ float xsm[32 * BX_STRIDE];
    int ntb = blockIdx.x, mt = blockIdx.y, z = blockIdx.z;
    int pr = z >> 2, b = z & 3;
    int t = threadIdx.x, warp = t >> 5, lane = t & 31;
    int gid = lane >> 2, tig = lane & 3;
    int n0 = ntb * 64;

    const float* W = g_Wt + pr * 65536 + mt * 128 * 256;
    const float* xb = g_xt + (size_t)b * CCH * NPIX;

    float s[8][4];
#pragma unroll
    for (int i = 0; i < 8; i++)
#pragma unroll
        for (int j = 0; j < 4; j++) s[i][j] = 0.f;

    for (int kk = 0; kk < 256; kk += 32) {
        if (kk) __syncthreads();
#pragma unroll
        for (int j = 0; j < 4; j++) {
            int idx = t + j * 256;
            int o = idx >> 3, cg = idx & 7;
            *(float4*)&wsm[o * AW_STRIDE + cg * 4] = *(const float4*)&W[o * 256 + kk + cg * 4];
        }
#pragma unroll
        for (int j = 0; j < 2; j++) {
            int idx = t + j * 256;
            int c = idx >> 4, ng = idx & 15;
            *(float4*)&xsm[c * BX_STRIDE + ng * 4] =
                *(const float4*)&xb[(size_t)(kk + c) * NPIX + n0 + ng * 4];
        }
        __syncthreads();
#pragma unroll
        for (int ks = 0; ks < 4; ks++) {
            uint32_t a[4];
            int ab = (warp * 16 + gid) * AW_STRIDE + ks * 8 + tig;
            a[0] = __float_as_uint(wsm[ab]);
            a[1] = __float_as_uint(wsm[ab + 8 * AW_STRIDE]);
            a[2] = __float_as_uint(wsm[ab + 4]);
            a[3] = __float_as_uint(wsm[ab + 8 * AW_STRIDE + 4]);
#pragma unroll
            for (int nt = 0; nt < 8; nt++) {
                int bbx = (ks * 8 + tig) * BX_STRIDE + nt * 8 + gid;
                mma_tf32(s[nt], a, __float_as_uint(xsm[bbx]),
                         __float_as_uint(xsm[bbx + 4 * BX_STRIDE]));
            }
        }
    }
    int o0 = mt * 128 + warp * 16 + gid, o1 = o0 + 8;
    const float* fg  = g_film + (b * 6 + 2 * pr) * 256;
    const float* fb2 = g_film + (b * 6 + 2 * pr + 1) * 256;
    const float* bias = (pr == 0) ? bq : (pr == 1) ? bk : bv;
    float g0 = fg[o0], g1 = fg[o1], e0 = fb2[o0], e1 = fb2[o1];
    float i0 = bias[o0], i1 = bias[o1];
    int h0 = o0 >> 5, d0 = o0 & 31, h1 = o1 >> 5, d1 = o1 & 31;
    float* outb = g_qkv + (size_t)pr * PR_STRIDE + (size_t)b * B_STRIDE;
    bool rnd = (pr != 0);
#pragma unroll
    for (int nt = 0; nt < 8; nt++) {
        int n = n0 + nt * 8 + 2 * tig;
        float v00 = g0 * (s[nt][0] + i0) + e0;
        float v01 = g0 * (s[nt][1] + i0) + e0;
        float v10 = g1 * (s[nt][2] + i1) + e1;
        float v11 = g1 * (s[nt][3] + i1) + e1;
        if (rnd) { v00 = tf32f(v00); v01 = tf32f(v01); v10 = tf32f(v10); v11 = tf32f(v11); }
        outb[((size_t)h0 * NPIX + n) * 32 + d0]     = v00;
        outb[((size_t)h0 * NPIX + n + 1) * 32 + d0] = v01;
        outb[((size_t)h1 * NPIX + n) * 32 + d1]     = v10;
        outb[((size_t)h1 * NPIX + n + 1) * 32 + d1] = v11;
    }
}

// ---------------------------------------------------------------------------
// 6) Flash attention with tf32 mma, cp.async double-buffered K/V/bias.
//    Smem layout (floats): stage0 [K 2304 | V 2560], stage1 [K | V],
//    psm 8704, bias0 64, bias1 64.
// ---------------------------------------------------------------------------
#define KS_STRIDE 36
#define VS_STRIDE 40
#define PS_STRIDE 68
#define STAGE_F   (64 * KS_STRIDE + 64 * VS_STRIDE)     // 4864 floats
#define PSM_OFF   (2 * STAGE_F)                          // 9728
#define BSM_OFF   (PSM_OFF + 8 * 16 * PS_STRIDE)         // 18432
#define ATTN_SMEM ((BSM_OFF + 128) * 4)                  // 74240 B

__global__ __launch_bounds__(256) void k_attn() {
    extern __shared__ float smp[];
    float* psm = smp + PSM_OFF;

    int t = threadIdx.x;
    int warp = t >> 5, lane = t & 31;
    int gid = lane >> 2, tig = lane & 3;
    int bh = blockIdx.y;
    int b = bh >> 3;

    const float* Qb = g_qkv + (size_t)bh * BH_STRIDE;
    const float* Kb = g_qkv + (size_t)PR_STRIDE + (size_t)bh * BH_STRIDE;
    const float* Vb = g_qkv + (size_t)2 * PR_STRIDE + (size_t)bh * BH_STRIDE;
    const float* bE = g_biasE + b * NPIX;

    uint32_t smb = (uint32_t)__cvta_generic_to_shared(smp);

    int qr = blockIdx.x * 128 + warp * 16 + gid;

    uint32_t aq[4][4];
#pragma unroll
    for (int ks = 0; ks < 4; ks++) {
        aq[ks][0] = tf32c(Qb[(size_t)qr * 32 + ks * 8 + tig] * QSC);
        aq[ks][1] = tf32c(Qb[(size_t)(qr + 8) * 32 + ks * 8 + tig] * QSC);
        aq[ks][2] = tf32c(Qb[(size_t)qr * 32 + ks * 8 + tig + 4] * QSC);
        aq[ks][3] = tf32c(Qb[(size_t)(qr + 8) * 32 + ks * 8 + tig + 4] * QSC);
    }

    float o[4][4];
#pragma unroll
    for (int i = 0; i < 4; i++)
#pragma unroll
        for (int j = 0; j < 4; j++) o[i][j] = 0.f;
    float m0 = -1e30f, m1 = -1e30f, l0 = 0.f, l1 = 0.f;

    float* pw = psm + warp * 16 * PS_STRIDE;

    // prologue: stage tile 0 into stage 0
    {
        const float4* Kg = (const float4*)Kb;
        const float4* Vg = (const float4*)Vb;
#pragma unroll
        for (int i = t; i < 512; i += 256) {
            int key = i >> 3, dq = i & 7;
            cpasync16(smb + (key * KS_STRIDE + dq * 4) * 4, Kg + i);
            cpasync16(smb + (64 * KS_STRIDE + key * VS_STRIDE + dq * 4) * 4, Vg + i);
        }
        if (t < 16) cpasync16(smb + (BSM_OFF + t * 4) * 4, bE + t * 4);
        CP_COMMIT();
        CP_WAIT0();
    }
    __syncthreads();

    for (int nk = 0; nk < 36; ++nk) {
        int cu = nk & 1, nx = cu ^ 1;
        // prefetch tile nk+1 into the other stage (overlapped with compute)
        if (nk < 35) {
            const float4* Kg = (const float4*)Kb + (nk + 1) * 512;
            const float4* Vg = (const float4*)Vb + (nk + 1) * 512;
            uint32_t ksu = smb + nx * STAGE_F * 4;
            uint32_t vsu = ksu + 64 * KS_STRIDE * 4;
#pragma unroll
            for (int i = t; i < 512; i += 256) {
                int key = i >> 3, dq = i & 7;
                cpasync16(ksu + (key * KS_STRIDE + dq * 4) * 4, Kg + i);
                cpasync16(vsu + (key * VS_STRIDE + dq * 4) * 4, Vg + i);
            }
            if (t < 16) cpasync16(smb + (BSM_OFF + nx * 64 + t * 4) * 4,
                                  bE + (nk + 1) * 64 + t * 4);
            CP_COMMIT();
        }

        const float* ksm = smp + cu * STAGE_F;
        const float* vsm = ksm + 64 * KS_STRIDE;
        const float* bsm = smp + BSM_OFF + cu * 64;

        float s[8][4];
#pragma unroll
        for (int nt = 0; nt < 8; nt++)
#pragma unroll
            for (int c = 0; c < 4; c++) s[nt][c] = 0.f;
#pragma unroll
        for (int ks = 0; ks < 4; ks++) {
#pragma unroll
            for (int nt = 0; nt < 8; nt++) {
                int kb = (nt * 8 + gid) * KS_STRIDE + ks * 8 + tig;
                uint32_t b0 = __float_as_uint(ksm[kb]);
                uint32_t b1 = __float_as_uint(ksm[kb + 4]);
                mma_tf32(s[nt], aq[ks], b0, b1);
            }
        }
        float mx0 = -1e30f, mx1 = -1e30f;
#pragma unroll
        for (int nt = 0; nt < 8; nt++) {
            float b0v = bsm[nt * 8 + 2 * tig];
            float b1v = bsm[nt * 8 + 2 * tig + 1];
            s[nt][0] += b0v; s[nt][1] += b1v;
            s[nt][2] += b0v; s[nt][3] += b1v;
            mx0 = fmaxf(mx0, fmaxf(s[nt][0], s[nt][1]));
            mx1 = fmaxf(mx1, fmaxf(s[nt][2], s[nt][3]));
        }
        mx0 = fmaxf(mx0, __shfl_xor_sync(0xffffffffu, mx0, 1));
        mx0 = fmaxf(mx0, __shfl_xor_sync(0xffffffffu, mx0, 2));
        mx1 = fmaxf(mx1, __shfl_xor_sync(0xffffffffu, mx1, 1));
        mx1 = fmaxf(mx1, __shfl_xor_sync(0xffffffffu, mx1, 2));

        float mn0 = fmaxf(m0, mx0), mn1 = fmaxf(m1, mx1);
        float c0 = ex2f(m0 - mn0), c1 = ex2f(m1 - mn1);
        m0 = mn0; m1 = mn1;

        float rs0 = 0.f, rs1 = 0.f;
#pragma unroll
        for (int nt = 0; nt < 8; nt++) {
            float p00 = ex2f(s[nt][0] - mn0);
            float p01 = ex2f(s[nt][1] - mn0);
            float p10 = ex2f(s[nt][2] - mn1);
            float p11 = ex2f(s[nt][3] - mn1);
            rs0 += p00 + p01; rs1 += p10 + p11;
            float2 lo, hi;
            lo.x = tf32f(p00); lo.y = tf32f(p01);
            hi.x = tf32f(p10); hi.y = tf32f(p11);
            *(float2*)&pw[gid * PS_STRIDE + nt * 8 + 2 * tig] = lo;
            *(float2*)&pw[(gid + 8) * PS_STRIDE + nt * 8 + 2 * tig] = hi;
        }
        rs0 += __shfl_xor_sync(0xffffffffu, rs0, 1);
        rs0 += __shfl_xor_sync(0xffffffffu, rs0, 2);
        rs1 += __shfl_xor_sync(0xffffffffu, rs1, 1);
        rs1 += __shfl_xor_sync(0xffffffffu, rs1, 2);
        l0 = l0 * c0 + rs0;
        l1 = l1 * c1 + rs1;
#pragma unroll
        for (int nt = 0; nt < 4; nt++) {
            o[nt][0] *= c0; o[nt][1] *= c0;
            o[nt][2] *= c1; o[nt][3] *= c1;
        }
        __syncwarp();

#pragma unroll
        for (int ks = 0; ks < 8; ks++) {
            uint32_t a[4];
            a[0] = __float_as_uint(pw[gid * PS_STRIDE + ks * 8 + tig]);
            a[1] = __float_as_uint(pw[(gid + 8) * PS_STRIDE + ks * 8 + tig]);
            a[2] = __float_as_uint(pw[gid * PS_STRIDE + ks * 8 + tig + 4]);
            a[3] = __float_as_uint(pw[(gid + 8) * PS_STRIDE + ks * 8 + tig + 4]);
#pragma unroll
            for (int nt = 0; nt < 4; nt++) {
                int vb = (ks * 8 + tig) * VS_STRIDE + nt * 8 + gid;
                uint32_t b0 = __float_as_uint(vsm[vb]);
                uint32_t b1 = __float_as_uint(vsm[vb + 4 * VS_STRIDE]);
                mma_tf32(o[nt], a, b0, b1);
            }
        }
        if (nk < 35) CP_WAIT0();
        __syncthreads();
    }

    float i0 = 1.0f / l0, i1 = 1.0f / l1;
    float* AO = g_ao + (size_t)bh * BH_STRIDE;
#pragma unroll
    for (int nt = 0; nt < 4; nt++) {
        float2 lo = make_float2(tf32f(o[nt][0] * i0), tf32f(o[nt][1] * i0));
        float2 hi = make_float2(tf32f(o[nt][2] * i1), tf32f(o[nt][3] * i1));
        *(float2*)&AO[(size_t)qr * 32 + nt * 8 + 2 * tig] = lo;
        *(float2*)&AO[(size_t)(qr + 8) * 32 + nt * 8 + 2 * tig] = hi;
    }
}

// ---------------------------------------------------------------------------
// 7) Output projection via tf32 mma
// ---------------------------------------------------------------------------
__global__ __launch_bounds__(256) void k_proj(const float* __restrict__ bproj,
                                              float* __restrict__ out) {
    __shared__ float wsm[128 * AW_STRIDE];
    __shared__ float bsm2[32 * BX_STRIDE];
    int ntb = blockIdx.x, mt = blockIdx.y, b = blockIdx.z;
    int t = threadIdx.x, warp = t >> 5, lane = t & 31;
    int gid = lane >> 2, tig = lane & 3;
    int n0 = ntb * 64;

    const float* W = g_Wt + 3 * 65536 + mt * 128 * 256;
    const float* AOb = g_ao + (size_t)b * B_STRIDE;

    float s[8][4];
#pragma unroll
    for (int i = 0; i < 8; i++)
#pragma unroll
        for (int j = 0; j < 4; j++) s[i][j] = 0.f;

    for (int kk = 0; kk < 256; kk += 32) {
        if (kk) __syncthreads();
#pragma unroll
        for (int j = 0; j < 4; j++) {
            int idx = t + j * 256;
            int o = idx >> 3, cg = idx & 7;
            *(float4*)&wsm[o * AW_STRIDE + cg * 4] = *(const float4*)&W[o * 256 + kk + cg * 4];
        }
#pragma unroll
        for (int j = 0; j < 8; j++) {
            int idx = t + j * 256;
            int c = idx >> 6, ng = idx & 63;
            int o = kk + c;
            bsm2[c * BX_STRIDE + ng] =
                AOb[((size_t)(o >> 5) * NPIX + n0 + ng) * 32 + (o & 31)];
        }
        __syncthreads();
#pragma unroll
        for (int ks = 0; ks < 4; ks++) {
            uint32_t a[4];
            int ab = (warp * 16 + gid) * AW_STRIDE + ks * 8 + tig;
            a[0] = __float_as_uint(wsm[ab]);
            a[1] = __float_as_uint(wsm[ab + 8 * AW_STRIDE]);
            a[2] = __float_as_uint(wsm[ab + 4]);
            a[3] = __float_as_uint(wsm[ab + 8 * AW_STRIDE + 4]);
#pragma unroll
            for (int nt = 0; nt < 8; nt++) {
                int bbx = (ks * 8 + tig) * BX_STRIDE + nt * 8 + gid;
                mma_tf32(s[nt], a, __float_as_uint(bsm2[bbx]),
                         __float_as_uint(bsm2[bbx + 4 * BX_STRIDE]));
            }
        }
    }
    int o0 = mt * 128 + warp * 16 + gid, o1 = o0 + 8;
    float bp0 = bproj[o0], bp1 = bproj[o1];
#pragma unroll
    for (int nt = 0; nt < 8; nt++) {
        int n = n0 + nt * 8 + 2 * tig;
        *(float2*)&out[((size_t)(b * 256 + o0)) * NPIX + n] =
            make_float2(s[nt][0] + bp0, s[nt][1] + bp0);
        *(float2*)&out[((size_t)(b * 256 + o1)) * NPIX + n] =
            make_float2(s[nt][2] + bp1, s[nt][3] + bp1);
    }
}

// ---------------------------------------------------------------------------
// launch
// ---------------------------------------------------------------------------
extern "C" void kernel_launch(void* const* d_in, const int* in_sizes, int n_in,
                              void* d_out, int out_size) {
    const float* x     = (const float*)d_in[0];
    const float* rgb   = (const float*)d_in[1];
    const float* wq    = (const float*)d_in[2];
    const float* bq    = (const float*)d_in[3];
    const float* wk    = (const float*)d_in[4];
    const float* bk    = (const float*)d_in[5];
    const float* wv    = (const float*)d_in[6];
    const float* bv    = (const float*)d_in[7];
    const float* wproj = (const float*)d_in[8];
    const float* bproj = (const float*)d_in[9];
    const float* c1w   = (const float*)d_in[10];
    const float* c1b   = (const float*)d_in[11];
    const float* c2w   = (const float*)d_in[12];
    const float* c2b   = (const float*)d_in[13];
    const float* alpha = (const float*)d_in[26];

    FilmArgs fa;
    fa.w[0] = (const float*)d_in[14]; fa.b[0] = (const float*)d_in[15];
    fa.w[1] = (const float*)d_in[16]; fa.b[1] = (const float*)d_in[17];
    fa.w[2] = (const float*)d_in[18]; fa.b[2] = (const float*)d_in[19];
    fa.w[3] = (const float*)d_in[20]; fa.b[3] = (const float*)d_in[21];
    fa.w[4] = (const float*)d_in[22]; fa.b[4] = (const float*)d_in[23];
    fa.w[5] = (const float*)d_in[24]; fa.b[5] = (const float*)d_in[25];

    static bool attr_done = false;
    if (!attr_done) {
        cudaFuncSetAttribute(k_attn, cudaFuncAttributeMaxDynamicSharedMemorySize, ATTN_SMEM);
        attr_done = true;
    }

    k_prep<<<2560, 256>>>(wq, wk, wv, wproj, x);
    k_lumabias<<<BSZ, 256>>>(rgb, alpha);
    k_conv1<<<dim3(HID, BSZ), 256>>>(c1w, c1b);
    k_conv2mean<<<dim3(32, BSZ, 6), 96>>>(c2w, c2b);
    k_film<<<dim3(6, BSZ), 256>>>(fa);
    k_qkv<<<dim3(36, 2, 12), 256>>>(bq, bk, bv);
    k_attn<<<dim3(18, 32), 256, ATTN_SMEM>>>();
    k_proj<<<dim3(36, 2, 4), 256>>>(bproj, (float*)d_out);
}